// round 8
// baseline (speedup 1.0000x reference)
#include <cuda_runtime.h>
#include <cuda_fp16.h>
#include <cstdint>

#define NT 4096
#define D  128
#define H  8
#define BN 64
#define NB (NT / BN)

// ---------------- scratch globals ---------------------------------------------
__device__ __align__(16) __half g_qh[H * NT * D];
__device__ __align__(16) __half g_ql[H * NT * D];
__device__ __align__(16) __half g_kh[H * NT * D];
__device__ __align__(16) __half g_kl[H * NT * D];
__device__ __align__(16) __half g_vh[H * D * NT];   // transposed [h][d][n]
__device__ __align__(16) float  g_o[H * NT * D];
__device__ float g_wgT[D * D];

__device__ __align__(16) __half g_xh[NT * D];
__device__ __align__(16) __half g_xl[NT * D];
__device__ __align__(16) __half g_wT[3][2][H * D * D];   // [which][hi/lo][h][dout][f]

// ---------------- helpers -------------------------------------------------------
__device__ __forceinline__ float ex2f(float x) {
    float y; asm("ex2.approx.ftz.f32 %0,%1;" : "=f"(y) : "f"(x)); return y;
}
#define CP16(d, s) asm volatile("cp.async.cg.shared.global [%0],[%1],16;" :: "r"(d), "l"(s) : "memory")
#define CPC()  asm volatile("cp.async.commit_group;" ::: "memory")
#define CPW0() asm volatile("cp.async.wait_group 0;" ::: "memory")
#define CPW1() asm volatile("cp.async.wait_group 1;" ::: "memory")

__device__ __forceinline__ uint32_t su32(const void* p) {
    return (uint32_t)__cvta_generic_to_shared(p);
}

__device__ __forceinline__ void mma(float* c, const uint32_t* a, uint32_t b0, uint32_t b1) {
    asm volatile(
        "mma.sync.aligned.m16n8k16.row.col.f32.f16.f16.f32 "
        "{%0,%1,%2,%3},{%4,%5,%6,%7},{%8,%9},{%0,%1,%2,%3};"
        : "+f"(c[0]), "+f"(c[1]), "+f"(c[2]), "+f"(c[3])
        : "r"(a[0]), "r"(a[1]), "r"(a[2]), "r"(a[3]), "r"(b0), "r"(b1));
}

__device__ __forceinline__ void pack2(float a, float b, uint32_t& hi, uint32_t& lo) {
    __half2 h = __floats2half2_rn(a, b);
    float2 f = __half22float2(h);
    __half2 r = __floats2half2_rn(a - f.x, b - f.y);
    hi = *(uint32_t*)&h; lo = *(uint32_t*)&r;
}

// ================== attention smem (per CTA, 2 CTAs/SM) =========================
// K stages x2: (Kh[64][136] | Kl[64][136]) ; V stages x2: [128][72]
#define KST    34816
#define OFF_V  (2 * KST)                // 69632
#define VST    18432
#define ASMEM  (OFF_V + 2 * VST)        // 106496

__device__ __forceinline__ void load_stage(uint32_t sb, int h, int kb, int tid) {
    size_t kof = (size_t)h * NT * D + (size_t)kb * BN * D;
    size_t vof = (size_t)h * D * NT + (size_t)kb * BN;
    uint32_t kbase = sb + (uint32_t)(kb & 1) * KST;
    uint32_t vbase = sb + OFF_V + (uint32_t)(kb & 1) * VST;
    for (int c = tid; c < 1024; c += 128) {          // K: 64 rows x 16 chunks
        int r = c >> 4, k = c & 15;
        uint32_t so = (uint32_t)(r * 272 + k * 16);
        CP16(kbase + so,         g_kh + kof + (size_t)r * D + k * 8);
        CP16(kbase + 17408 + so, g_kl + kof + (size_t)r * D + k * 8);
    }
    for (int c = tid; c < 1024; c += 128) {          // V: 128 dim-rows x 8 chunks
        int r = c >> 3, k = c & 7;
        CP16(vbase + (uint32_t)(r * 144 + k * 16), g_vh + vof + (size_t)r * NT + k * 8);
    }
}

// ---------------- attention: grid (64, 8), 128 threads, 2 CTAs/SM ---------------
__global__ void __launch_bounds__(128, 2) attn_kernel(const float* __restrict__ W_m) {
    extern __shared__ char sm[];
    const int tid = threadIdx.x, w = tid >> 5, l = tid & 31;
    const int h = blockIdx.y, q0 = blockIdx.x * 64;
    const int lq = l >> 2, lr = l & 3;
    const uint32_t sb = su32(sm);
    const float L2E = 1.4426950408889634f;

    // Q fragments hi/lo (regs)
    uint32_t qa[2][8][4];
#pragma unroll
    for (int s = 0; s < 2; s++) {
        const __half* qs = (s ? g_ql : g_qh) + ((size_t)h * NT + q0 + w * 16) * D;
#pragma unroll
        for (int j = 0; j < 8; j++) {
            const __half* base = qs + (size_t)lq * D + j * 16 + lr * 2;
            qa[s][j][0] = *(const uint32_t*)(base);
            qa[s][j][1] = *(const uint32_t*)(base + 8 * D);
            qa[s][j][2] = *(const uint32_t*)(base + 8);
            qa[s][j][3] = *(const uint32_t*)(base + 8 * D + 8);
        }
    }

    load_stage(sb, h, 0, tid); CPC();

    float o[16][4];
#pragma unroll
    for (int t = 0; t < 16; t++) { o[t][0] = o[t][1] = o[t][2] = o[t][3] = 0.f; }
    float m0 = -1e30f, m1 = -1e30f, l0 = 0.f, l1 = 0.f;

    for (int kb = 0; kb < NB; kb++) {
        __syncthreads();
        if (kb + 1 < NB) load_stage(sb, h, kb + 1, tid);
        CPC(); CPW1();
        __syncthreads();

        const char* stg = sm + (kb & 1) * KST;
        const uint32_t* Kh32 = (const uint32_t*)(stg);
        const uint32_t* Kl32 = (const uint32_t*)(stg + 17408);
        const uint32_t* Vh32 = (const uint32_t*)(sm + OFF_V + (kb & 1) * VST);

        // ---- S = QhKh + QlKh + QhKl ----
        float s[8][4];
#pragma unroll
        for (int t = 0; t < 8; t++) { s[t][0] = s[t][1] = s[t][2] = s[t][3] = 0.f; }
#pragma unroll
        for (int t = 0; t < 8; t++) {
            int krow = 8 * t + lq;
#pragma unroll
            for (int j = 0; j < 8; j++) {
                int bi = krow * 68 + j * 8 + lr;
                uint32_t b0 = Kh32[bi], b1 = Kh32[bi + 4];
                uint32_t c0 = Kl32[bi], c1 = Kl32[bi + 4];
                mma(s[t], qa[0][j], b0, b1);
                mma(s[t], qa[1][j], b0, b1);
                mma(s[t], qa[0][j], c0, c1);
            }
        }

        // ---- online softmax ----
        float rx0 = -1e30f, rx1 = -1e30f;
#pragma unroll
        for (int t = 0; t < 8; t++) {
            rx0 = fmaxf(rx0, fmaxf(s[t][0], s[t][1]));
            rx1 = fmaxf(rx1, fmaxf(s[t][2], s[t][3]));
        }
        rx0 = fmaxf(rx0, __shfl_xor_sync(~0u, rx0, 1));
        rx0 = fmaxf(rx0, __shfl_xor_sync(~0u, rx0, 2));
        rx1 = fmaxf(rx1, __shfl_xor_sync(~0u, rx1, 1));
        rx1 = fmaxf(rx1, __shfl_xor_sync(~0u, rx1, 2));
        float mn0 = fmaxf(m0, rx0), mn1 = fmaxf(m1, rx1);
        float sc0 = ex2f((m0 - mn0) * L2E), sc1 = ex2f((m1 - mn1) * L2E);
        m0 = mn0; m1 = mn1;
        float rs0 = 0.f, rs1 = 0.f;
#pragma unroll
        for (int t = 0; t < 8; t++) {
            s[t][0] = ex2f((s[t][0] - mn0) * L2E);
            s[t][1] = ex2f((s[t][1] - mn0) * L2E);
            s[t][2] = ex2f((s[t][2] - mn1) * L2E);
            s[t][3] = ex2f((s[t][3] - mn1) * L2E);
            rs0 += s[t][0] + s[t][1];
            rs1 += s[t][2] + s[t][3];
        }
        rs0 += __shfl_xor_sync(~0u, rs0, 1); rs0 += __shfl_xor_sync(~0u, rs0, 2);
        rs1 += __shfl_xor_sync(~0u, rs1, 1); rs1 += __shfl_xor_sync(~0u, rs1, 2);
        l0 = l0 * sc0 + rs0; l1 = l1 * sc1 + rs1;
#pragma unroll
        for (int t = 0; t < 16; t++) {
            o[t][0] *= sc0; o[t][1] *= sc0; o[t][2] *= sc1; o[t][3] *= sc1;
        }

        uint32_t ph[4][4], pl[4][4];
#pragma unroll
        for (int j = 0; j < 4; j++) {
            pack2(s[2 * j][0],     s[2 * j][1],     ph[j][0], pl[j][0]);
            pack2(s[2 * j][2],     s[2 * j][3],     ph[j][1], pl[j][1]);
            pack2(s[2 * j + 1][0], s[2 * j + 1][1], ph[j][2], pl[j][2]);
            pack2(s[2 * j + 1][2], s[2 * j + 1][3], ph[j][3], pl[j][3]);
        }

        // ---- O += PhVh + PlVh ----
#pragma unroll
        for (int t = 0; t < 16; t++) {
            int vr = 8 * t + lq;
#pragma unroll
            for (int j = 0; j < 4; j++) {
                int bi = vr * 36 + j * 8 + lr;
                uint32_t b0 = Vh32[bi], b1 = Vh32[bi + 4];
                mma(o[t], ph[j], b0, b1);
                mma(o[t], pl[j], b0, b1);
            }
        }
    }

    float wm = W_m[h];
    float i0 = wm / l0, i1 = wm / l1;
    float* og = g_o + ((size_t)h * NT + q0 + w * 16) * D;
#pragma unroll
    for (int t = 0; t < 16; t++) {
        int col = 8 * t + lr * 2;
        *(float2*)(og + (size_t)lq * D + col)       = make_float2(o[t][0] * i0, o[t][1] * i0);
        *(float2*)(og + (size_t)(lq + 8) * D + col) = make_float2(o[t][2] * i1, o[t][3] * i1);
    }
}

// ================== prep: split x, split+transpose W ============================
__global__ void __launch_bounds__(256) splitx_kernel(const float* __restrict__ x) {
    int base = (blockIdx.x * 256 + threadIdx.x) * 8;
    float4 a = *(const float4*)(x + base);
    float4 b = *(const float4*)(x + base + 4);
    float v[8] = {a.x, a.y, a.z, a.w, b.x, b.y, b.z, b.w};
    __align__(16) __half hb[8], lb[8];
#pragma unroll
    for (int i = 0; i < 8; i++) {
        __half hh = __float2half_rn(v[i]);
        hb[i] = hh;
        lb[i] = __float2half_rn(v[i] - __half2float(hh));
    }
    *(uint4*)(g_xh + base) = *(uint4*)hb;
    *(uint4*)(g_xl + base) = *(uint4*)lb;
}

__global__ void __launch_bounds__(256) splitW_kernel(const float* __restrict__ Wk,
                                                     const float* __restrict__ Wq,
                                                     const float* __restrict__ Wv) {
    const int h = blockIdx.x, which = blockIdx.y;
    const float* W = (which == 0 ? Wq : which == 1 ? Wk : Wv) + (size_t)h * D * D;
    __half* oh = g_wT[which][0] + (size_t)h * D * D;
    __half* ol = g_wT[which][1] + (size_t)h * D * D;
    for (int idx = threadIdx.x; idx < D * D; idx += 256) {
        int dout = idx >> 7, f = idx & 127;
        float v = W[(size_t)f * D + dout];
        __half hh = __float2half_rn(v);
        oh[idx] = hh;
        ol[idx] = __float2half_rn(v - __half2float(hh));
    }
}

// ================== qkv via HMMA: grid (32, 8, 3), 256 threads ==================
#define WROW 136
#define QST  (128 * WROW * 2)
#define QSMEM (2 * QST)
#define TP 133

__global__ void __launch_bounds__(256) qkv_mma_kernel() {
    extern __shared__ char sm[];
    const int tid = threadIdx.x, w = tid >> 5, l = tid & 31;
    const int tile = blockIdx.x, h = blockIdx.y, which = blockIdx.z;
    const int lq = l >> 2, lr = l & 3;
    const int n0 = tile * 128;

    {
        const uint32_t sb = su32(sm);
        const __half* wh = g_wT[which][0] + (size_t)h * D * D;
        const __half* wl = g_wT[which][1] + (size_t)h * D * D;
        for (int c = tid; c < 2048; c += 256) {
            int r = c >> 4, k = c & 15;
            uint32_t so = (uint32_t)(r * (WROW * 2) + k * 16);
            CP16(sb + so,       wh + (size_t)r * D + k * 8);
            CP16(sb + QST + so, wl + (size_t)r * D + k * 8);
        }
        CPC();
    }

    uint32_t xa[2][8][4];
#pragma unroll
    for (int s = 0; s < 2; s++) {
        const __half* xs = (s ? g_xl : g_xh) + (size_t)(n0 + w * 16) * D;
#pragma unroll
        for (int j = 0; j < 8; j++) {
            const __half* base = xs + (size_t)lq * D + j * 16 + lr * 2;
            xa[s][j][0] = *(const uint32_t*)(base);
            xa[s][j][1] = *(const uint32_t*)(base + 8 * D);
            xa[s][j][2] = *(const uint32_t*)(base + 8);
            xa[s][j][3] = *(const uint32_t*)(base + 8 * D + 8);
        }
    }

    CPW0();
    __syncthreads();

    const uint32_t* Wh32 = (const uint32_t*)(sm);
    const uint32_t* Wl32 = (const uint32_t*)(sm + QST);

    float s[16][4];
#pragma unroll
    for (int t = 0; t < 16; t++) { s[t][0] = s[t][1] = s[t][2] = s[t][3] = 0.f; }
#pragma unroll
    for (int t = 0; t < 16; t++) {
        int nrow = 8 * t + lq;
#pragma unroll
        for (int j = 0; j < 8; j++) {
            int bi = nrow * (WROW / 2) + j * 8 + lr;
            uint32_t b0 = Wh32[bi], b1 = Wh32[bi + 4];
            uint32_t c0 = Wl32[bi], c1 = Wl32[bi + 4];
            mma(s[t], xa[0][j], b0, b1);
            mma(s[t], xa[1][j], b0, b1);
            mma(s[t], xa[0][j], c0, c1);
        }
    }

    if (which < 2) {
        __half* oh = (which == 0 ? g_qh : g_kh) + ((size_t)h * NT + n0 + w * 16) * D;
        __half* ol = (which == 0 ? g_ql : g_kl) + ((size_t)h * NT + n0 + w * 16) * D;
#pragma unroll
        for (int t = 0; t < 16; t++) {
            int col = 8 * t + lr * 2;
            uint32_t h01, l01, h23, l23;
            pack2(s[t][0], s[t][1], h01, l01);
            pack2(s[t][2], s[t][3], h23, l23);
            *(uint32_t*)(oh + (size_t)lq * D + col)       = h01;
            *(uint32_t*)(ol + (size_t)lq * D + col)       = l01;
            *(uint32_t*)(oh + (size_t)(lq + 8) * D + col) = h23;
            *(uint32_t*)(ol + (size_t)(lq + 8) * D + col) = l23;
        }
    } else {
        __syncthreads();
        float* buf = (float*)sm;
#pragma unroll
        for (int t = 0; t < 16; t++) {
            int c = 8 * t + lr * 2;
            int r0 = w * 16 + lq, r1 = r0 + 8;
            buf[r0 * TP + c] = s[t][0]; buf[r0 * TP + c + 1] = s[t][1];
            buf[r1 * TP + c] = s[t][2]; buf[r1 * TP + c + 1] = s[t][3];
        }
        __syncthreads();
#pragma unroll
        for (int dd = 0; dd < 16; dd++) {
            int d = w * 16 + dd;
            int n4 = l * 4;
            __align__(8) __half hb[4];
#pragma unroll
            for (int i = 0; i < 4; i++)
                hb[i] = __float2half_rn(buf[(n4 + i) * TP + d]);
            *(uint2*)(g_vh + ((size_t)h * D + d) * NT + n0 + n4) = *(uint2*)hb;
        }
    }
}

// ---------------- Wg transpose + final MLP --------------------------------------
__global__ void wgT_kernel(const float* __restrict__ Wg) {
    for (int it = threadIdx.x; it < D * D; it += blockDim.x) {
        int d = it >> 7, f = it & 127;
        g_wgT[f * D + d] = Wg[d * D + f];
    }
}

__global__ void __launch_bounds__(256) final_kernel(const float* __restrict__ x,
                                                    const float* __restrict__ bg,
                                                    float* __restrict__ y) {
    __shared__ float hs[64][D];
    __shared__ float Ws[16][D];
    __shared__ float bsh[D];
    const int n0 = blockIdx.x * 64;
    const int tid = threadIdx.x;

    for (int it = tid; it < 64 * 32; it += 256) {
        int r = it >> 5, c4 = it & 31;
        size_t off = (size_t)(n0 + r) * D + c4 * 4;
        float4 a = *(const float4*)(x + off);
#pragma unroll
        for (int hh = 0; hh < H; hh++) {
            float4 b = *(const float4*)(g_o + (size_t)hh * NT * D + off);
            a.x += b.x; a.y += b.y; a.z += b.z; a.w += b.w;
        }
        *(float4*)&hs[r][c4 * 4] = a;
    }
    if (tid < D) bsh[tid] = bg[tid];

    const int ty = tid >> 4, tx = tid & 15;
    float acc[4][8];
#pragma unroll
    for (int i = 0; i < 4; i++)
#pragma unroll
        for (int j = 0; j < 8; j++) acc[i][j] = 0.f;

    for (int fc = 0; fc < 8; fc++) {
        __syncthreads();
        for (int it = tid; it < 16 * 32; it += 256) {
            int r = it >> 5, c4 = it & 31;
            *(float4*)&Ws[r][c4 * 4] = *(const float4*)(g_wgT + (size_t)(fc * 16 + r) * D + c4 * 4);
        }
        __syncthreads();
#pragma unroll
        for (int f = 0; f < 16; f++) {
            float a[4];
#pragma unroll
            for (int ii = 0; ii < 4; ii++) a[ii] = hs[ty * 4 + ii][fc * 16 + f];
            float4 b0 = *(float4*)&Ws[f][tx * 8];
            float4 b1 = *(float4*)&Ws[f][tx * 8 + 4];
            float b[8] = {b0.x, b0.y, b0.z, b0.w, b1.x, b1.y, b1.z, b1.w};
#pragma unroll
            for (int ii = 0; ii < 4; ii++)
#pragma unroll
                for (int jj = 0; jj < 8; jj++)
                    acc[ii][jj] = fmaf(a[ii], b[jj], acc[ii][jj]);
        }
    }

#pragma unroll
    for (int ii = 0; ii < 4; ii++) {
        int n = n0 + ty * 4 + ii;
#pragma unroll
        for (int jj = 0; jj < 8; jj += 4) {
            int d = tx * 8 + jj;
            float4 xv = *(const float4*)(x + (size_t)n * D + d);
            float4 r;
            r.x = xv.x + fmaxf(acc[ii][jj + 0] + bsh[d + 0], 0.f);
            r.y = xv.y + fmaxf(acc[ii][jj + 1] + bsh[d + 1], 0.f);
            r.z = xv.z + fmaxf(acc[ii][jj + 2] + bsh[d + 2], 0.f);
            r.w = xv.w + fmaxf(acc[ii][jj + 3] + bsh[d + 3], 0.f);
            *(float4*)(y + (size_t)n * D + d) = r;
        }
    }
}

// ---------------- launch ---------------------------------------------------------
extern "C" void kernel_launch(void* const* d_in, const int* in_sizes, int n_in,
                              void* d_out, int out_size) {
    const float* x  = (const float*)d_in[0];
    const float* Wk = (const float*)d_in[1];
    const float* Wq = (const float*)d_in[2];
    const float* Wv = (const float*)d_in[3];
    const float* Wm = (const float*)d_in[4];
    const float* Wg = (const float*)d_in[5];
    const float* bg = (const float*)d_in[6];
    float* y = (float*)d_out;

    cudaFuncSetAttribute(attn_kernel, cudaFuncAttributeMaxDynamicSharedMemorySize, ASMEM);
    cudaFuncSetAttribute(qkv_mma_kernel, cudaFuncAttributeMaxDynamicSharedMemorySize, QSMEM);

    splitx_kernel<<<NT * D / (256 * 8), 256>>>(x);
    splitW_kernel<<<dim3(H, 3), 256>>>(Wk, Wq, Wv);
    qkv_mma_kernel<<<dim3(NT / 128, H, 3), 256, QSMEM>>>();
    attn_kernel<<<dim3(NT / 64, H), 128, ASMEM>>>(Wm);
    wgT_kernel<<<1, 256>>>(Wg);
    final_kernel<<<NT / 64, 256>>>(x, bg, y);
}

// round 9
// speedup vs baseline: 1.0238x; 1.0238x over previous
#include <cuda_runtime.h>
#include <cuda_fp16.h>
#include <cstdint>

#define NT 4096
#define D  128
#define H  8
#define BN 64
#define NB (NT / BN)

// ---------------- scratch globals ---------------------------------------------
__device__ __align__(16) __half g_qh[H * NT * D];
__device__ __align__(16) __half g_ql[H * NT * D];
__device__ __align__(16) __half g_kh[H * NT * D];
__device__ __align__(16) __half g_kl[H * NT * D];
__device__ __align__(16) __half g_vh[H * D * NT];   // transposed [h][d][n]
__device__ __align__(16) float  g_o[H * NT * D];
__device__ float g_wgT[D * D];

__device__ __align__(16) __half g_xh[NT * D];
__device__ __align__(16) __half g_xl[NT * D];
__device__ __align__(16) __half g_wT[3][2][H * D * D];   // [which][hi/lo][h][dout][f]

// ---------------- helpers -------------------------------------------------------
__device__ __forceinline__ float ex2f(float x) {
    float y; asm("ex2.approx.ftz.f32 %0,%1;" : "=f"(y) : "f"(x)); return y;
}
#define CP16(d, s) asm volatile("cp.async.cg.shared.global [%0],[%1],16;" :: "r"(d), "l"(s) : "memory")
#define CPC()  asm volatile("cp.async.commit_group;" ::: "memory")
#define CPW0() asm volatile("cp.async.wait_group 0;" ::: "memory")
#define CPW1() asm volatile("cp.async.wait_group 1;" ::: "memory")

__device__ __forceinline__ uint32_t su32(const void* p) {
    return (uint32_t)__cvta_generic_to_shared(p);
}

__device__ __forceinline__ void mma(float* c, const uint32_t* a, uint32_t b0, uint32_t b1) {
    asm volatile(
        "mma.sync.aligned.m16n8k16.row.col.f32.f16.f16.f32 "
        "{%0,%1,%2,%3},{%4,%5,%6,%7},{%8,%9},{%0,%1,%2,%3};"
        : "+f"(c[0]), "+f"(c[1]), "+f"(c[2]), "+f"(c[3])
        : "r"(a[0]), "r"(a[1]), "r"(a[2]), "r"(a[3]), "r"(b0), "r"(b1));
}

__device__ __forceinline__ void pack2(float a, float b, uint32_t& hi, uint32_t& lo) {
    __half2 h = __floats2half2_rn(a, b);
    float2 f = __half22float2(h);
    __half2 r = __floats2half2_rn(a - f.x, b - f.y);
    hi = *(uint32_t*)&h; lo = *(uint32_t*)&r;
}

// ================== attention smem =================================================
// K stages x2: (Kh[64][136] | Kl[64][136]) ; V stages x2: [128][72]
#define KST    34816
#define OFF_V  (2 * KST)                // 69632
#define VST    18432
#define ASMEM  (OFF_V + 2 * VST)        // 106496

__device__ __forceinline__ void load_stage(uint32_t sb, int h, int kb, int tid) {
    size_t kof = (size_t)h * NT * D + (size_t)kb * BN * D;
    size_t vof = (size_t)h * D * NT + (size_t)kb * BN;
    uint32_t kbase = sb + (uint32_t)(kb & 1) * KST;
    uint32_t vbase = sb + OFF_V + (uint32_t)(kb & 1) * VST;
    for (int c = tid; c < 1024; c += 256) {          // K: 64 rows x 16 chunks
        int r = c >> 4, k = c & 15;
        uint32_t so = (uint32_t)(r * 272 + k * 16);
        CP16(kbase + so,         g_kh + kof + (size_t)r * D + k * 8);
        CP16(kbase + 17408 + so, g_kl + kof + (size_t)r * D + k * 8);
    }
    for (int c = tid; c < 1024; c += 256) {          // V: 128 dim-rows x 8 chunks
        int r = c >> 3, k = c & 7;
        CP16(vbase + (uint32_t)(r * 144 + k * 16), g_vh + vof + (size_t)r * NT + k * 8);
    }
}

// ---------------- attention: grid (32, 8), 256 threads --------------------------
__global__ void __launch_bounds__(256) attn_kernel(const float* __restrict__ W_m) {
    extern __shared__ char sm[];
    const int tid = threadIdx.x, w = tid >> 5, l = tid & 31;
    const int h = blockIdx.y, q0 = blockIdx.x * 128;
    const int lq = l >> 2, lr = l & 3;
    const uint32_t sb = su32(sm);
    const float L2E = 1.4426950408889634f;

    // Q fragments hi/lo (regs)
    uint32_t qa[2][8][4];
#pragma unroll
    for (int s = 0; s < 2; s++) {
        const __half* qs = (s ? g_ql : g_qh) + ((size_t)h * NT + q0 + w * 16) * D;
#pragma unroll
        for (int j = 0; j < 8; j++) {
            const __half* base = qs + (size_t)lq * D + j * 16 + lr * 2;
            qa[s][j][0] = *(const uint32_t*)(base);
            qa[s][j][1] = *(const uint32_t*)(base + 8 * D);
            qa[s][j][2] = *(const uint32_t*)(base + 8);
            qa[s][j][3] = *(const uint32_t*)(base + 8 * D + 8);
        }
    }

    load_stage(sb, h, 0, tid); CPC();

    float o[16][4];
#pragma unroll
    for (int t = 0; t < 16; t++) { o[t][0] = o[t][1] = o[t][2] = o[t][3] = 0.f; }
    float m0 = -1e30f, m1 = -1e30f, l0 = 0.f, l1 = 0.f;

    for (int kb = 0; kb < NB; kb++) {
        __syncthreads();
        if (kb + 1 < NB) load_stage(sb, h, kb + 1, tid);
        CPC(); CPW1();
        __syncthreads();

        const char* stg = sm + (kb & 1) * KST;
        const uint32_t* Kh32 = (const uint32_t*)(stg);
        const uint32_t* Kl32 = (const uint32_t*)(stg + 17408);
        const uint32_t* Vh32 = (const uint32_t*)(sm + OFF_V + (kb & 1) * VST);

        // ---- S = QhKh + QlKh + QhKl — accumulator-interleaved sweeps ----
        float s[8][4];
#pragma unroll
        for (int t = 0; t < 8; t++) { s[t][0] = s[t][1] = s[t][2] = s[t][3] = 0.f; }
#pragma unroll
        for (int j = 0; j < 8; j++) {
            uint32_t bh[8][2];
#pragma unroll
            for (int t = 0; t < 8; t++) {
                int bi = (8 * t + lq) * 68 + j * 8 + lr;
                bh[t][0] = Kh32[bi]; bh[t][1] = Kh32[bi + 4];
            }
#pragma unroll
            for (int t = 0; t < 8; t++) mma(s[t], qa[0][j], bh[t][0], bh[t][1]);
#pragma unroll
            for (int t = 0; t < 8; t++) mma(s[t], qa[1][j], bh[t][0], bh[t][1]);
#pragma unroll
            for (int t = 0; t < 8; t++) {
                int bi = (8 * t + lq) * 68 + j * 8 + lr;
                mma(s[t], qa[0][j], Kl32[bi], Kl32[bi + 4]);
            }
        }

        // ---- online softmax ----
        float rx0 = -1e30f, rx1 = -1e30f;
#pragma unroll
        for (int t = 0; t < 8; t++) {
            rx0 = fmaxf(rx0, fmaxf(s[t][0], s[t][1]));
            rx1 = fmaxf(rx1, fmaxf(s[t][2], s[t][3]));
        }
        rx0 = fmaxf(rx0, __shfl_xor_sync(~0u, rx0, 1));
        rx0 = fmaxf(rx0, __shfl_xor_sync(~0u, rx0, 2));
        rx1 = fmaxf(rx1, __shfl_xor_sync(~0u, rx1, 1));
        rx1 = fmaxf(rx1, __shfl_xor_sync(~0u, rx1, 2));
        float mn0 = fmaxf(m0, rx0), mn1 = fmaxf(m1, rx1);
        float sc0 = ex2f((m0 - mn0) * L2E), sc1 = ex2f((m1 - mn1) * L2E);
        m0 = mn0; m1 = mn1;
        float rs0 = 0.f, rs1 = 0.f;
#pragma unroll
        for (int t = 0; t < 8; t++) {
            s[t][0] = ex2f((s[t][0] - mn0) * L2E);
            s[t][1] = ex2f((s[t][1] - mn0) * L2E);
            s[t][2] = ex2f((s[t][2] - mn1) * L2E);
            s[t][3] = ex2f((s[t][3] - mn1) * L2E);
            rs0 += s[t][0] + s[t][1];
            rs1 += s[t][2] + s[t][3];
        }
        rs0 += __shfl_xor_sync(~0u, rs0, 1); rs0 += __shfl_xor_sync(~0u, rs0, 2);
        rs1 += __shfl_xor_sync(~0u, rs1, 1); rs1 += __shfl_xor_sync(~0u, rs1, 2);
        l0 = l0 * sc0 + rs0; l1 = l1 * sc1 + rs1;
#pragma unroll
        for (int t = 0; t < 16; t++) {
            o[t][0] *= sc0; o[t][1] *= sc0; o[t][2] *= sc1; o[t][3] *= sc1;
        }

        uint32_t ph[4][4], pl[4][4];
#pragma unroll
        for (int j = 0; j < 4; j++) {
            pack2(s[2 * j][0],     s[2 * j][1],     ph[j][0], pl[j][0]);
            pack2(s[2 * j][2],     s[2 * j][3],     ph[j][1], pl[j][1]);
            pack2(s[2 * j + 1][0], s[2 * j + 1][1], ph[j][2], pl[j][2]);
            pack2(s[2 * j + 1][2], s[2 * j + 1][3], ph[j][3], pl[j][3]);
        }

        // ---- O += PhVh + PlVh — accumulator-interleaved sweeps ----
#pragma unroll
        for (int j = 0; j < 4; j++) {
            uint32_t vb[16][2];
#pragma unroll
            for (int t = 0; t < 16; t++) {
                int bi = (8 * t + lq) * 36 + j * 8 + lr;
                vb[t][0] = Vh32[bi]; vb[t][1] = Vh32[bi + 4];
            }
#pragma unroll
            for (int t = 0; t < 16; t++) mma(o[t], ph[j], vb[t][0], vb[t][1]);
#pragma unroll
            for (int t = 0; t < 16; t++) mma(o[t], pl[j], vb[t][0], vb[t][1]);
        }
    }

    float wm = W_m[h];
    float i0 = wm / l0, i1 = wm / l1;
    float* og = g_o + ((size_t)h * NT + q0 + w * 16) * D;
#pragma unroll
    for (int t = 0; t < 16; t++) {
        int col = 8 * t + lr * 2;
        *(float2*)(og + (size_t)lq * D + col)       = make_float2(o[t][0] * i0, o[t][1] * i0);
        *(float2*)(og + (size_t)(lq + 8) * D + col) = make_float2(o[t][2] * i1, o[t][3] * i1);
    }
}

// ================== prep: split x, split+transpose W ============================
__global__ void __launch_bounds__(256) splitx_kernel(const float* __restrict__ x) {
    int base = (blockIdx.x * 256 + threadIdx.x) * 8;
    float4 a = *(const float4*)(x + base);
    float4 b = *(const float4*)(x + base + 4);
    float v[8] = {a.x, a.y, a.z, a.w, b.x, b.y, b.z, b.w};
    __align__(16) __half hb[8], lb[8];
#pragma unroll
    for (int i = 0; i < 8; i++) {
        __half hh = __float2half_rn(v[i]);
        hb[i] = hh;
        lb[i] = __float2half_rn(v[i] - __half2float(hh));
    }
    *(uint4*)(g_xh + base) = *(uint4*)hb;
    *(uint4*)(g_xl + base) = *(uint4*)lb;
}

__global__ void __launch_bounds__(256) splitW_kernel(const float* __restrict__ Wk,
                                                     const float* __restrict__ Wq,
                                                     const float* __restrict__ Wv) {
    const int h = blockIdx.x, which = blockIdx.y;
    const float* W = (which == 0 ? Wq : which == 1 ? Wk : Wv) + (size_t)h * D * D;
    __half* oh = g_wT[which][0] + (size_t)h * D * D;
    __half* ol = g_wT[which][1] + (size_t)h * D * D;
    for (int idx = threadIdx.x; idx < D * D; idx += 256) {
        int dout = idx >> 7, f = idx & 127;
        float v = W[(size_t)f * D + dout];
        __half hh = __float2half_rn(v);
        oh[idx] = hh;
        ol[idx] = __float2half_rn(v - __half2float(hh));
    }
}

// ================== qkv via HMMA: grid (32, 8, 3), 256 threads ==================
#define WROW 136
#define QST  (128 * WROW * 2)
#define QSMEM (2 * QST)
#define TP 133

__global__ void __launch_bounds__(256) qkv_mma_kernel() {
    extern __shared__ char sm[];
    const int tid = threadIdx.x, w = tid >> 5, l = tid & 31;
    const int tile = blockIdx.x, h = blockIdx.y, which = blockIdx.z;
    const int lq = l >> 2, lr = l & 3;
    const int n0 = tile * 128;

    {
        const uint32_t sb = su32(sm);
        const __half* wh = g_wT[which][0] + (size_t)h * D * D;
        const __half* wl = g_wT[which][1] + (size_t)h * D * D;
        for (int c = tid; c < 2048; c += 256) {
            int r = c >> 4, k = c & 15;
            uint32_t so = (uint32_t)(r * (WROW * 2) + k * 16);
            CP16(sb + so,       wh + (size_t)r * D + k * 8);
            CP16(sb + QST + so, wl + (size_t)r * D + k * 8);
        }
        CPC();
    }

    uint32_t xa[2][8][4];
#pragma unroll
    for (int s = 0; s < 2; s++) {
        const __half* xs = (s ? g_xl : g_xh) + (size_t)(n0 + w * 16) * D;
#pragma unroll
        for (int j = 0; j < 8; j++) {
            const __half* base = xs + (size_t)lq * D + j * 16 + lr * 2;
            xa[s][j][0] = *(const uint32_t*)(base);
            xa[s][j][1] = *(const uint32_t*)(base + 8 * D);
            xa[s][j][2] = *(const uint32_t*)(base + 8);
            xa[s][j][3] = *(const uint32_t*)(base + 8 * D + 8);
        }
    }

    CPW0();
    __syncthreads();

    const uint32_t* Wh32 = (const uint32_t*)(sm);
    const uint32_t* Wl32 = (const uint32_t*)(sm + QST);

    float s[16][4];
#pragma unroll
    for (int t = 0; t < 16; t++) { s[t][0] = s[t][1] = s[t][2] = s[t][3] = 0.f; }
    // accumulator-interleaved: j outer, t sweeps inside
#pragma unroll
    for (int j = 0; j < 8; j++) {
#pragma unroll
        for (int t = 0; t < 16; t++) {
            int bi = (8 * t + lq) * (WROW / 2) + j * 8 + lr;
            mma(s[t], xa[0][j], Wh32[bi], Wh32[bi + 4]);
        }
#pragma unroll
        for (int t = 0; t < 16; t++) {
            int bi = (8 * t + lq) * (WROW / 2) + j * 8 + lr;
            mma(s[t], xa[1][j], Wh32[bi], Wh32[bi + 4]);
        }
#pragma unroll
        for (int t = 0; t < 16; t++) {
            int bi = (8 * t + lq) * (WROW / 2) + j * 8 + lr;
            mma(s[t], xa[0][j], Wl32[bi], Wl32[bi + 4]);
        }
    }

    if (which < 2) {
        __half* oh = (which == 0 ? g_qh : g_kh) + ((size_t)h * NT + n0 + w * 16) * D;
        __half* ol = (which == 0 ? g_ql : g_kl) + ((size_t)h * NT + n0 + w * 16) * D;
#pragma unroll
        for (int t = 0; t < 16; t++) {
            int col = 8 * t + lr * 2;
            uint32_t h01, l01, h23, l23;
            pack2(s[t][0], s[t][1], h01, l01);
            pack2(s[t][2], s[t][3], h23, l23);
            *(uint32_t*)(oh + (size_t)lq * D + col)       = h01;
            *(uint32_t*)(ol + (size_t)lq * D + col)       = l01;
            *(uint32_t*)(oh + (size_t)(lq + 8) * D + col) = h23;
            *(uint32_t*)(ol + (size_t)(lq + 8) * D + col) = l23;
        }
    } else {
        __syncthreads();
        float* buf = (float*)sm;
#pragma unroll
        for (int t = 0; t < 16; t++) {
            int c = 8 * t + lr * 2;
            int r0 = w * 16 + lq, r1 = r0 + 8;
            buf[r0 * TP + c] = s[t][0]; buf[r0 * TP + c + 1] = s[t][1];
            buf[r1 * TP + c] = s[t][2]; buf[r1 * TP + c + 1] = s[t][3];
        }
        __syncthreads();
#pragma unroll
        for (int dd = 0; dd < 16; dd++) {
            int d = w * 16 + dd;
            int n4 = l * 4;
            __align__(8) __half hb[4];
#pragma unroll
            for (int i = 0; i < 4; i++)
                hb[i] = __float2half_rn(buf[(n4 + i) * TP + d]);
            *(uint2*)(g_vh + ((size_t)h * D + d) * NT + n0 + n4) = *(uint2*)hb;
        }
    }
}

// ---------------- Wg transpose + final MLP --------------------------------------
__global__ void wgT_kernel(const float* __restrict__ Wg) {
    for (int it = threadIdx.x; it < D * D; it += blockDim.x) {
        int d = it >> 7, f = it & 127;
        g_wgT[f * D + d] = Wg[d * D + f];
    }
}

__global__ void __launch_bounds__(256) final_kernel(const float* __restrict__ x,
                                                    const float* __restrict__ bg,
                                                    float* __restrict__ y) {
    __shared__ float hs[64][D];
    __shared__ float Ws[16][D];
    __shared__ float bsh[D];
    const int n0 = blockIdx.x * 64;
    const int tid = threadIdx.x;

    for (int it = tid; it < 64 * 32; it += 256) {
        int r = it >> 5, c4 = it & 31;
        size_t off = (size_t)(n0 + r) * D + c4 * 4;
        float4 a = *(const float4*)(x + off);
#pragma unroll
        for (int hh = 0; hh < H; hh++) {
            float4 b = *(const float4*)(g_o + (size_t)hh * NT * D + off);
            a.x += b.x; a.y += b.y; a.z += b.z; a.w += b.w;
        }
        *(float4*)&hs[r][c4 * 4] = a;
    }
    if (tid < D) bsh[tid] = bg[tid];

    const int ty = tid >> 4, tx = tid & 15;
    float acc[4][8];
#pragma unroll
    for (int i = 0; i < 4; i++)
#pragma unroll
        for (int j = 0; j < 8; j++) acc[i][j] = 0.f;

    for (int fc = 0; fc < 8; fc++) {
        __syncthreads();
        for (int it = tid; it < 16 * 32; it += 256) {
            int r = it >> 5, c4 = it & 31;
            *(float4*)&Ws[r][c4 * 4] = *(const float4*)(g_wgT + (size_t)(fc * 16 + r) * D + c4 * 4);
        }
        __syncthreads();
#pragma unroll
        for (int f = 0; f < 16; f++) {
            float a[4];
#pragma unroll
            for (int ii = 0; ii < 4; ii++) a[ii] = hs[ty * 4 + ii][fc * 16 + f];
            float4 b0 = *(float4*)&Ws[f][tx * 8];
            float4 b1 = *(float4*)&Ws[f][tx * 8 + 4];
            float b[8] = {b0.x, b0.y, b0.z, b0.w, b1.x, b1.y, b1.z, b1.w};
#pragma unroll
            for (int ii = 0; ii < 4; ii++)
#pragma unroll
                for (int jj = 0; jj < 8; jj++)
                    acc[ii][jj] = fmaf(a[ii], b[jj], acc[ii][jj]);
        }
    }

#pragma unroll
    for (int ii = 0; ii < 4; ii++) {
        int n = n0 + ty * 4 + ii;
#pragma unroll
        for (int jj = 0; jj < 8; jj += 4) {
            int d = tx * 8 + jj;
            float4 xv = *(const float4*)(x + (size_t)n * D + d);
            float4 r;
            r.x = xv.x + fmaxf(acc[ii][jj + 0] + bsh[d + 0], 0.f);
            r.y = xv.y + fmaxf(acc[ii][jj + 1] + bsh[d + 1], 0.f);
            r.z = xv.z + fmaxf(acc[ii][jj + 2] + bsh[d + 2], 0.f);
            r.w = xv.w + fmaxf(acc[ii][jj + 3] + bsh[d + 3], 0.f);
            *(float4*)(y + (size_t)n * D + d) = r;
        }
    }
}

// ---------------- launch ---------------------------------------------------------
extern "C" void kernel_launch(void* const* d_in, const int* in_sizes, int n_in,
                              void* d_out, int out_size) {
    const float* x  = (const float*)d_in[0];
    const float* Wk = (const float*)d_in[1];
    const float* Wq = (const float*)d_in[2];
    const float* Wv = (const float*)d_in[3];
    const float* Wm = (const float*)d_in[4];
    const float* Wg = (const float*)d_in[5];
    const float* bg = (const float*)d_in[6];
    float* y = (float*)d_out;

    cudaFuncSetAttribute(attn_kernel, cudaFuncAttributeMaxDynamicSharedMemorySize, ASMEM);
    cudaFuncSetAttribute(qkv_mma_kernel, cudaFuncAttributeMaxDynamicSharedMemorySize, QSMEM);

    splitx_kernel<<<NT * D / (256 * 8), 256>>>(x);
    splitW_kernel<<<dim3(H, 3), 256>>>(Wk, Wq, Wv);
    qkv_mma_kernel<<<dim3(NT / 128, H, 3), 256, QSMEM>>>();
    attn_kernel<<<dim3(NT / 128, H), 256, ASMEM>>>(Wm);
    wgT_kernel<<<1, 256>>>(Wg);
    final_kernel<<<NT / 64, 256>>>(x, bg, y);
}

// round 10
// speedup vs baseline: 1.0391x; 1.0149x over previous
#include <cuda_runtime.h>
#include <cuda_fp16.h>
#include <cstdint>

#define NT 4096
#define D  128
#define H  8
#define BN 64
#define NB (NT / BN)

// ---------------- scratch globals ---------------------------------------------
__device__ __align__(16) __half g_qh[H * NT * D];
__device__ __align__(16) __half g_ql[H * NT * D];
__device__ __align__(16) __half g_kh[H * NT * D];
__device__ __align__(16) __half g_kl[H * NT * D];
__device__ __align__(16) __half g_vh[H * D * NT];   // transposed [h][d][n]
__device__ __align__(16) float  g_o[H * NT * D];
__device__ float g_wgT[D * D];

__device__ __align__(16) __half g_xh[NT * D];
__device__ __align__(16) __half g_xl[NT * D];
__device__ __align__(16) __half g_wT[3][2][H * D * D];   // [which][hi/lo][h][dout][f]

// ---------------- helpers -------------------------------------------------------
__device__ __forceinline__ float ex2f(float x) {
    float y; asm("ex2.approx.ftz.f32 %0,%1;" : "=f"(y) : "f"(x)); return y;
}
#define CP16(d, s) asm volatile("cp.async.cg.shared.global [%0],[%1],16;" :: "r"(d), "l"(s) : "memory")
#define CPC()  asm volatile("cp.async.commit_group;" ::: "memory")
#define CPW0() asm volatile("cp.async.wait_group 0;" ::: "memory")
#define CPW1() asm volatile("cp.async.wait_group 1;" ::: "memory")

__device__ __forceinline__ uint32_t su32(const void* p) {
    return (uint32_t)__cvta_generic_to_shared(p);
}

__device__ __forceinline__ void mma(float* c, const uint32_t* a, uint32_t b0, uint32_t b1) {
    asm volatile(
        "mma.sync.aligned.m16n8k16.row.col.f32.f16.f16.f32 "
        "{%0,%1,%2,%3},{%4,%5,%6,%7},{%8,%9},{%0,%1,%2,%3};"
        : "+f"(c[0]), "+f"(c[1]), "+f"(c[2]), "+f"(c[3])
        : "r"(a[0]), "r"(a[1]), "r"(a[2]), "r"(a[3]), "r"(b0), "r"(b1));
}

__device__ __forceinline__ void pack2(float a, float b, uint32_t& hi, uint32_t& lo) {
    __half2 h = __floats2half2_rn(a, b);
    float2 f = __half22float2(h);
    __half2 r = __floats2half2_rn(a - f.x, b - f.y);
    hi = *(uint32_t*)&h; lo = *(uint32_t*)&r;
}

// ================== attention smem (per CTA; 2 CTAs/SM) =========================
// K stages x2: (Kh[64][136] | Kl[64][136]) ; V stages x2: [128][72]
#define KST    34816
#define OFF_V  (2 * KST)                // 69632
#define VST    18432
#define ASMEM  (OFF_V + 2 * VST)        // 106496

__device__ __forceinline__ void load_stage(uint32_t sb, int h, int kb, int tid) {
    size_t kof = (size_t)h * NT * D + (size_t)kb * BN * D;
    size_t vof = (size_t)h * D * NT + (size_t)kb * BN;
    uint32_t kbase = sb + (uint32_t)(kb & 1) * KST;
    uint32_t vbase = sb + OFF_V + (uint32_t)(kb & 1) * VST;
    for (int c = tid; c < 1024; c += 128) {          // K: 64 rows x 16 chunks
        int r = c >> 4, k = c & 15;
        uint32_t so = (uint32_t)(r * 272 + k * 16);
        CP16(kbase + so,         g_kh + kof + (size_t)r * D + k * 8);
        CP16(kbase + 17408 + so, g_kl + kof + (size_t)r * D + k * 8);
    }
    for (int c = tid; c < 1024; c += 128) {          // V: 128 dim-rows x 8 chunks
        int r = c >> 3, k = c & 7;
        CP16(vbase + (uint32_t)(r * 144 + k * 16), g_vh + vof + (size_t)r * NT + k * 8);
    }
}

// ---------------- attention: grid (64, 8), 128 threads, 2 CTAs/SM ---------------
__global__ void __launch_bounds__(128, 2) attn_kernel(const float* __restrict__ W_m) {
    extern __shared__ char sm[];
    const int tid = threadIdx.x, w = tid >> 5, l = tid & 31;
    const int h = blockIdx.y, q0 = blockIdx.x * 64;
    const int lq = l >> 2, lr = l & 3;
    const uint32_t sb = su32(sm);
    const float L2E = 1.4426950408889634f;

    // Q fragments hi/lo (regs)
    uint32_t qa[2][8][4];
#pragma unroll
    for (int s = 0; s < 2; s++) {
        const __half* qs = (s ? g_ql : g_qh) + ((size_t)h * NT + q0 + w * 16) * D;
#pragma unroll
        for (int j = 0; j < 8; j++) {
            const __half* base = qs + (size_t)lq * D + j * 16 + lr * 2;
            qa[s][j][0] = *(const uint32_t*)(base);
            qa[s][j][1] = *(const uint32_t*)(base + 8 * D);
            qa[s][j][2] = *(const uint32_t*)(base + 8);
            qa[s][j][3] = *(const uint32_t*)(base + 8 * D + 8);
        }
    }

    load_stage(sb, h, 0, tid); CPC();

    float o[16][4];
#pragma unroll
    for (int t = 0; t < 16; t++) { o[t][0] = o[t][1] = o[t][2] = o[t][3] = 0.f; }
    float m0 = -1e30f, m1 = -1e30f, l0 = 0.f, l1 = 0.f;

    for (int kb = 0; kb < NB; kb++) {
        __syncthreads();
        if (kb + 1 < NB) load_stage(sb, h, kb + 1, tid);
        CPC(); CPW1();
        __syncthreads();

        const char* stg = sm + (kb & 1) * KST;
        const uint32_t* Kh32 = (const uint32_t*)(stg);
        const uint32_t* Kl32 = (const uint32_t*)(stg + 17408);
        const uint32_t* Vh32 = (const uint32_t*)(sm + OFF_V + (kb & 1) * VST);

        // ---- S = QhKh + QlKh + QhKl — accumulator-interleaved sweeps ----
        float s[8][4];
#pragma unroll
        for (int t = 0; t < 8; t++) { s[t][0] = s[t][1] = s[t][2] = s[t][3] = 0.f; }
#pragma unroll
        for (int j = 0; j < 8; j++) {
            uint32_t bh[8][2];
#pragma unroll
            for (int t = 0; t < 8; t++) {
                int bi = (8 * t + lq) * 68 + j * 8 + lr;
                bh[t][0] = Kh32[bi]; bh[t][1] = Kh32[bi + 4];
            }
#pragma unroll
            for (int t = 0; t < 8; t++) mma(s[t], qa[0][j], bh[t][0], bh[t][1]);
#pragma unroll
            for (int t = 0; t < 8; t++) mma(s[t], qa[1][j], bh[t][0], bh[t][1]);
#pragma unroll
            for (int t = 0; t < 8; t++) {
                int bi = (8 * t + lq) * 68 + j * 8 + lr;
                mma(s[t], qa[0][j], Kl32[bi], Kl32[bi + 4]);
            }
        }

        // ---- online softmax ----
        float rx0 = -1e30f, rx1 = -1e30f;
#pragma unroll
        for (int t = 0; t < 8; t++) {
            rx0 = fmaxf(rx0, fmaxf(s[t][0], s[t][1]));
            rx1 = fmaxf(rx1, fmaxf(s[t][2], s[t][3]));
        }
        rx0 = fmaxf(rx0, __shfl_xor_sync(~0u, rx0, 1));
        rx0 = fmaxf(rx0, __shfl_xor_sync(~0u, rx0, 2));
        rx1 = fmaxf(rx1, __shfl_xor_sync(~0u, rx1, 1));
        rx1 = fmaxf(rx1, __shfl_xor_sync(~0u, rx1, 2));
        float mn0 = fmaxf(m0, rx0), mn1 = fmaxf(m1, rx1);
        float sc0 = ex2f((m0 - mn0) * L2E), sc1 = ex2f((m1 - mn1) * L2E);
        m0 = mn0; m1 = mn1;
        float rs0 = 0.f, rs1 = 0.f;
#pragma unroll
        for (int t = 0; t < 8; t++) {
            s[t][0] = ex2f((s[t][0] - mn0) * L2E);
            s[t][1] = ex2f((s[t][1] - mn0) * L2E);
            s[t][2] = ex2f((s[t][2] - mn1) * L2E);
            s[t][3] = ex2f((s[t][3] - mn1) * L2E);
            rs0 += s[t][0] + s[t][1];
            rs1 += s[t][2] + s[t][3];
        }
        rs0 += __shfl_xor_sync(~0u, rs0, 1); rs0 += __shfl_xor_sync(~0u, rs0, 2);
        rs1 += __shfl_xor_sync(~0u, rs1, 1); rs1 += __shfl_xor_sync(~0u, rs1, 2);
        l0 = l0 * sc0 + rs0; l1 = l1 * sc1 + rs1;
#pragma unroll
        for (int t = 0; t < 16; t++) {
            o[t][0] *= sc0; o[t][1] *= sc0; o[t][2] *= sc1; o[t][3] *= sc1;
        }

        uint32_t ph[4][4], pl[4][4];
#pragma unroll
        for (int j = 0; j < 4; j++) {
            pack2(s[2 * j][0],     s[2 * j][1],     ph[j][0], pl[j][0]);
            pack2(s[2 * j][2],     s[2 * j][3],     ph[j][1], pl[j][1]);
            pack2(s[2 * j + 1][0], s[2 * j + 1][1], ph[j][2], pl[j][2]);
            pack2(s[2 * j + 1][2], s[2 * j + 1][3], ph[j][3], pl[j][3]);
        }

        // ---- O += PhVh + PlVh — accumulator-interleaved sweeps ----
#pragma unroll
        for (int j = 0; j < 4; j++) {
            uint32_t vb[16][2];
#pragma unroll
            for (int t = 0; t < 16; t++) {
                int bi = (8 * t + lq) * 36 + j * 8 + lr;
                vb[t][0] = Vh32[bi]; vb[t][1] = Vh32[bi + 4];
            }
#pragma unroll
            for (int t = 0; t < 16; t++) mma(o[t], ph[j], vb[t][0], vb[t][1]);
#pragma unroll
            for (int t = 0; t < 16; t++) mma(o[t], pl[j], vb[t][0], vb[t][1]);
        }
    }

    float wm = W_m[h];
    float i0 = wm / l0, i1 = wm / l1;
    float* og = g_o + ((size_t)h * NT + q0 + w * 16) * D;
#pragma unroll
    for (int t = 0; t < 16; t++) {
        int col = 8 * t + lr * 2;
        *(float2*)(og + (size_t)lq * D + col)       = make_float2(o[t][0] * i0, o[t][1] * i0);
        *(float2*)(og + (size_t)(lq + 8) * D + col) = make_float2(o[t][2] * i1, o[t][3] * i1);
    }
}

// ================== prep: split x, split+transpose W ============================
__global__ void __launch_bounds__(256) splitx_kernel(const float* __restrict__ x) {
    int base = (blockIdx.x * 256 + threadIdx.x) * 8;
    float4 a = *(const float4*)(x + base);
    float4 b = *(const float4*)(x + base + 4);
    float v[8] = {a.x, a.y, a.z, a.w, b.x, b.y, b.z, b.w};
    __align__(16) __half hb[8], lb[8];
#pragma unroll
    for (int i = 0; i < 8; i++) {
        __half hh = __float2half_rn(v[i]);
        hb[i] = hh;
        lb[i] = __float2half_rn(v[i] - __half2float(hh));
    }
    *(uint4*)(g_xh + base) = *(uint4*)hb;
    *(uint4*)(g_xl + base) = *(uint4*)lb;
}

__global__ void __launch_bounds__(256) splitW_kernel(const float* __restrict__ Wk,
                                                     const float* __restrict__ Wq,
                                                     const float* __restrict__ Wv) {
    const int h = blockIdx.x, which = blockIdx.y;
    const float* W = (which == 0 ? Wq : which == 1 ? Wk : Wv) + (size_t)h * D * D;
    __half* oh = g_wT[which][0] + (size_t)h * D * D;
    __half* ol = g_wT[which][1] + (size_t)h * D * D;
    for (int idx = threadIdx.x; idx < D * D; idx += 256) {
        int dout = idx >> 7, f = idx & 127;
        float v = W[(size_t)f * D + dout];
        __half hh = __float2half_rn(v);
        oh[idx] = hh;
        ol[idx] = __float2half_rn(v - __half2float(hh));
    }
}

// ================== qkv via HMMA: grid (32, 8, 3), 256 threads ==================
#define WROW 136
#define QST  (128 * WROW * 2)
#define QSMEM (2 * QST)
#define TP 133

__global__ void __launch_bounds__(256) qkv_mma_kernel() {
    extern __shared__ char sm[];
    const int tid = threadIdx.x, w = tid >> 5, l = tid & 31;
    const int tile = blockIdx.x, h = blockIdx.y, which = blockIdx.z;
    const int lq = l >> 2, lr = l & 3;
    const int n0 = tile * 128;

    {
        const uint32_t sb = su32(sm);
        const __half* wh = g_wT[which][0] + (size_t)h * D * D;
        const __half* wl = g_wT[which][1] + (size_t)h * D * D;
        for (int c = tid; c < 2048; c += 256) {
            int r = c >> 4, k = c & 15;
            uint32_t so = (uint32_t)(r * (WROW * 2) + k * 16);
            CP16(sb + so,       wh + (size_t)r * D + k * 8);
            CP16(sb + QST + so, wl + (size_t)r * D + k * 8);
        }
        CPC();
    }

    uint32_t xa[2][8][4];
#pragma unroll
    for (int s = 0; s < 2; s++) {
        const __half* xs = (s ? g_xl : g_xh) + (size_t)(n0 + w * 16) * D;
#pragma unroll
        for (int j = 0; j < 8; j++) {
            const __half* base = xs + (size_t)lq * D + j * 16 + lr * 2;
            xa[s][j][0] = *(const uint32_t*)(base);
            xa[s][j][1] = *(const uint32_t*)(base + 8 * D);
            xa[s][j][2] = *(const uint32_t*)(base + 8);
            xa[s][j][3] = *(const uint32_t*)(base + 8 * D + 8);
        }
    }

    CPW0();
    __syncthreads();

    const uint32_t* Wh32 = (const uint32_t*)(sm);
    const uint32_t* Wl32 = (const uint32_t*)(sm + QST);

    float s[16][4];
#pragma unroll
    for (int t = 0; t < 16; t++) { s[t][0] = s[t][1] = s[t][2] = s[t][3] = 0.f; }
#pragma unroll
    for (int j = 0; j < 8; j++) {
#pragma unroll
        for (int t = 0; t < 16; t++) {
            int bi = (8 * t + lq) * (WROW / 2) + j * 8 + lr;
            mma(s[t], xa[0][j], Wh32[bi], Wh32[bi + 4]);
        }
#pragma unroll
        for (int t = 0; t < 16; t++) {
            int bi = (8 * t + lq) * (WROW / 2) + j * 8 + lr;
            mma(s[t], xa[1][j], Wh32[bi], Wh32[bi + 4]);
        }
#pragma unroll
        for (int t = 0; t < 16; t++) {
            int bi = (8 * t + lq) * (WROW / 2) + j * 8 + lr;
            mma(s[t], xa[0][j], Wl32[bi], Wl32[bi + 4]);
        }
    }

    if (which < 2) {
        __half* oh = (which == 0 ? g_qh : g_kh) + ((size_t)h * NT + n0 + w * 16) * D;
        __half* ol = (which == 0 ? g_ql : g_kl) + ((size_t)h * NT + n0 + w * 16) * D;
#pragma unroll
        for (int t = 0; t < 16; t++) {
            int col = 8 * t + lr * 2;
            uint32_t h01, l01, h23, l23;
            pack2(s[t][0], s[t][1], h01, l01);
            pack2(s[t][2], s[t][3], h23, l23);
            *(uint32_t*)(oh + (size_t)lq * D + col)       = h01;
            *(uint32_t*)(ol + (size_t)lq * D + col)       = l01;
            *(uint32_t*)(oh + (size_t)(lq + 8) * D + col) = h23;
            *(uint32_t*)(ol + (size_t)(lq + 8) * D + col) = l23;
        }
    } else {
        __syncthreads();
        float* buf = (float*)sm;
#pragma unroll
        for (int t = 0; t < 16; t++) {
            int c = 8 * t + lr * 2;
            int r0 = w * 16 + lq, r1 = r0 + 8;
            buf[r0 * TP + c] = s[t][0]; buf[r0 * TP + c + 1] = s[t][1];
            buf[r1 * TP + c] = s[t][2]; buf[r1 * TP + c + 1] = s[t][3];
        }
        __syncthreads();
#pragma unroll
        for (int dd = 0; dd < 16; dd++) {
            int d = w * 16 + dd;
            int n4 = l * 4;
            __align__(8) __half hb[4];
#pragma unroll
            for (int i = 0; i < 4; i++)
                hb[i] = __float2half_rn(buf[(n4 + i) * TP + d]);
            *(uint2*)(g_vh + ((size_t)h * D + d) * NT + n0 + n4) = *(uint2*)hb;
        }
    }
}

// ---------------- Wg transpose + final MLP --------------------------------------
__global__ void wgT_kernel(const float* __restrict__ Wg) {
    for (int it = threadIdx.x; it < D * D; it += blockDim.x) {
        int d = it >> 7, f = it & 127;
        g_wgT[f * D + d] = Wg[d * D + f];
    }
}

__global__ void __launch_bounds__(256) final_kernel(const float* __restrict__ x,
                                                    const float* __restrict__ bg,
                                                    float* __restrict__ y) {
    __shared__ float hs[64][D];
    __shared__ float Ws[16][D];
    __shared__ float bsh[D];
    const int n0 = blockIdx.x * 64;
    const int tid = threadIdx.x;

    for (int it = tid; it < 64 * 32; it += 256) {
        int r = it >> 5, c4 = it & 31;
        size_t off = (size_t)(n0 + r) * D + c4 * 4;
        float4 a = *(const float4*)(x + off);
#pragma unroll
        for (int hh = 0; hh < H; hh++) {
            float4 b = *(const float4*)(g_o + (size_t)hh * NT * D + off);
            a.x += b.x; a.y += b.y; a.z += b.z; a.w += b.w;
        }
        *(float4*)&hs[r][c4 * 4] = a;
    }
    if (tid < D) bsh[tid] = bg[tid];

    const int ty = tid >> 4, tx = tid & 15;
    float acc[4][8];
#pragma unroll
    for (int i = 0; i < 4; i++)
#pragma unroll
        for (int j = 0; j < 8; j++) acc[i][j] = 0.f;

    for (int fc = 0; fc < 8; fc++) {
        __syncthreads();
        for (int it = tid; it < 16 * 32; it += 256) {
            int r = it >> 5, c4 = it & 31;
            *(float4*)&Ws[r][c4 * 4] = *(const float4*)(g_wgT + (size_t)(fc * 16 + r) * D + c4 * 4);
        }
        __syncthreads();
#pragma unroll
        for (int f = 0; f < 16; f++) {
            float a[4];
#pragma unroll
            for (int ii = 0; ii < 4; ii++) a[ii] = hs[ty * 4 + ii][fc * 16 + f];
            float4 b0 = *(float4*)&Ws[f][tx * 8];
            float4 b1 = *(float4*)&Ws[f][tx * 8 + 4];
            float b[8] = {b0.x, b0.y, b0.z, b0.w, b1.x, b1.y, b1.z, b1.w};
#pragma unroll
            for (int ii = 0; ii < 4; ii++)
#pragma unroll
                for (int jj = 0; jj < 8; jj++)
                    acc[ii][jj] = fmaf(a[ii], b[jj], acc[ii][jj]);
        }
    }

#pragma unroll
    for (int ii = 0; ii < 4; ii++) {
        int n = n0 + ty * 4 + ii;
#pragma unroll
        for (int jj = 0; jj < 8; jj += 4) {
            int d = tx * 8 + jj;
            float4 xv = *(const float4*)(x + (size_t)n * D + d);
            float4 r;
            r.x = xv.x + fmaxf(acc[ii][jj + 0] + bsh[d + 0], 0.f);
            r.y = xv.y + fmaxf(acc[ii][jj + 1] + bsh[d + 1], 0.f);
            r.z = xv.z + fmaxf(acc[ii][jj + 2] + bsh[d + 2], 0.f);
            r.w = xv.w + fmaxf(acc[ii][jj + 3] + bsh[d + 3], 0.f);
            *(float4*)(y + (size_t)n * D + d) = r;
        }
    }
}

// ---------------- launch ---------------------------------------------------------
extern "C" void kernel_launch(void* const* d_in, const int* in_sizes, int n_in,
                              void* d_out, int out_size) {
    const float* x  = (const float*)d_in[0];
    const float* Wk = (const float*)d_in[1];
    const float* Wq = (const float*)d_in[2];
    const float* Wv = (const float*)d_in[3];
    const float* Wm = (const float*)d_in[4];
    const float* Wg = (const float*)d_in[5];
    const float* bg = (const float*)d_in[6];
    float* y = (float*)d_out;

    cudaFuncSetAttribute(attn_kernel, cudaFuncAttributeMaxDynamicSharedMemorySize, ASMEM);
    cudaFuncSetAttribute(qkv_mma_kernel, cudaFuncAttributeMaxDynamicSharedMemorySize, QSMEM);

    splitx_kernel<<<NT * D / (256 * 8), 256>>>(x);
    splitW_kernel<<<dim3(H, 3), 256>>>(Wk, Wq, Wv);
    qkv_mma_kernel<<<dim3(NT / 128, H, 3), 256, QSMEM>>>();
    attn_kernel<<<dim3(NT / 64, H), 128, ASMEM>>>(Wm);
    wgT_kernel<<<1, 256>>>(Wg);
    final_kernel<<<NT / 64, 256>>>(x, bg, y);
}

// round 11
// speedup vs baseline: 1.2528x; 1.2057x over previous
#include <cuda_runtime.h>
#include <cuda_fp16.h>
#include <cstdint>

#define NT 4096
#define D  128
#define H  8
#define BN 64
#define NB (NT / BN)

// ---------------- scratch globals ---------------------------------------------
__device__ __align__(16) __half g_qh[H * NT * D];
__device__ __align__(16) __half g_ql[H * NT * D];
__device__ __align__(16) __half g_kh[H * NT * D];
__device__ __align__(16) __half g_vh[H * D * NT];   // transposed [h][d][n]
__device__ __align__(16) float  g_o[H * NT * D];
__device__ float g_wgT[D * D];

__device__ __align__(16) __half g_xh[NT * D];
__device__ __align__(16) __half g_xl[NT * D];
__device__ __align__(16) __half g_wT[3][2][H * D * D];   // [which][hi/lo][h][dout][f]

// ---------------- helpers -------------------------------------------------------
__device__ __forceinline__ float ex2f(float x) {
    float y; asm("ex2.approx.ftz.f32 %0,%1;" : "=f"(y) : "f"(x)); return y;
}
#define CP16(d, s) asm volatile("cp.async.cg.shared.global [%0],[%1],16;" :: "r"(d), "l"(s) : "memory")
#define CPC()  asm volatile("cp.async.commit_group;" ::: "memory")
#define CPW0() asm volatile("cp.async.wait_group 0;" ::: "memory")
#define CPW1() asm volatile("cp.async.wait_group 1;" ::: "memory")

__device__ __forceinline__ uint32_t su32(const void* p) {
    return (uint32_t)__cvta_generic_to_shared(p);
}

__device__ __forceinline__ void mma(float* c, const uint32_t* a, uint32_t b0, uint32_t b1) {
    asm volatile(
        "mma.sync.aligned.m16n8k16.row.col.f32.f16.f16.f32 "
        "{%0,%1,%2,%3},{%4,%5,%6,%7},{%8,%9},{%0,%1,%2,%3};"
        : "+f"(c[0]), "+f"(c[1]), "+f"(c[2]), "+f"(c[3])
        : "r"(a[0]), "r"(a[1]), "r"(a[2]), "r"(a[3]), "r"(b0), "r"(b1));
}

__device__ __forceinline__ void pack2(float a, float b, uint32_t& hi, uint32_t& lo) {
    __half2 h = __floats2half2_rn(a, b);
    float2 f = __half22float2(h);
    __half2 r = __floats2half2_rn(a - f.x, b - f.y);
    hi = *(uint32_t*)&h; lo = *(uint32_t*)&r;
}

// ================== attention smem (per CTA; 2 CTAs/SM) =========================
// K stages x2: Kh[64][136] ; V stages x2: [128][72]
#define KST    17408
#define OFF_V  (2 * KST)                // 34816
#define VST    18432
#define ASMEM  (OFF_V + 2 * VST)        // 71680

__device__ __forceinline__ void load_stage(uint32_t sb, int h, int kb, int tid) {
    size_t kof = (size_t)h * NT * D + (size_t)kb * BN * D;
    size_t vof = (size_t)h * D * NT + (size_t)kb * BN;
    uint32_t kbase = sb + (uint32_t)(kb & 1) * KST;
    uint32_t vbase = sb + OFF_V + (uint32_t)(kb & 1) * VST;
    for (int c = tid; c < 1024; c += 128) {          // Kh: 64 rows x 16 chunks
        int r = c >> 4, k = c & 15;
        CP16(kbase + (uint32_t)(r * 272 + k * 16), g_kh + kof + (size_t)r * D + k * 8);
    }
    for (int c = tid; c < 1024; c += 128) {          // V: 128 dim-rows x 8 chunks
        int r = c >> 3, k = c & 7;
        CP16(vbase + (uint32_t)(r * 144 + k * 16), g_vh + vof + (size_t)r * NT + k * 8);
    }
}

// ---------------- attention: grid (64, 8), 128 threads, 2 CTAs/SM ---------------
__global__ void __launch_bounds__(128, 2) attn_kernel(const float* __restrict__ W_m) {
    extern __shared__ char sm[];
    const int tid = threadIdx.x, w = tid >> 5, l = tid & 31;
    const int h = blockIdx.y, q0 = blockIdx.x * 64;
    const int lq = l >> 2, lr = l & 3;
    const uint32_t sb = su32(sm);
    const float L2E = 1.4426950408889634f;

    // Q fragments hi/lo (regs)
    uint32_t qa[2][8][4];
#pragma unroll
    for (int s = 0; s < 2; s++) {
        const __half* qs = (s ? g_ql : g_qh) + ((size_t)h * NT + q0 + w * 16) * D;
#pragma unroll
        for (int j = 0; j < 8; j++) {
            const __half* base = qs + (size_t)lq * D + j * 16 + lr * 2;
            qa[s][j][0] = *(const uint32_t*)(base);
            qa[s][j][1] = *(const uint32_t*)(base + 8 * D);
            qa[s][j][2] = *(const uint32_t*)(base + 8);
            qa[s][j][3] = *(const uint32_t*)(base + 8 * D + 8);
        }
    }

    load_stage(sb, h, 0, tid); CPC();

    float o[16][4];
#pragma unroll
    for (int t = 0; t < 16; t++) { o[t][0] = o[t][1] = o[t][2] = o[t][3] = 0.f; }
    float m0 = -1e30f, m1 = -1e30f, l0 = 0.f, l1 = 0.f;

    for (int kb = 0; kb < NB; kb++) {
        __syncthreads();
        if (kb + 1 < NB) load_stage(sb, h, kb + 1, tid);
        CPC(); CPW1();
        __syncthreads();

        const uint32_t* Kh32 = (const uint32_t*)(sm + (kb & 1) * KST);
        const uint32_t* Vh32 = (const uint32_t*)(sm + OFF_V + (kb & 1) * VST);

        // ---- S = QhKh + QlKh — accumulator-interleaved sweeps ----
        float s[8][4];
#pragma unroll
        for (int t = 0; t < 8; t++) { s[t][0] = s[t][1] = s[t][2] = s[t][3] = 0.f; }
#pragma unroll
        for (int j = 0; j < 8; j++) {
            uint32_t bh[8][2];
#pragma unroll
            for (int t = 0; t < 8; t++) {
                int bi = (8 * t + lq) * 68 + j * 8 + lr;
                bh[t][0] = Kh32[bi]; bh[t][1] = Kh32[bi + 4];
            }
#pragma unroll
            for (int t = 0; t < 8; t++) mma(s[t], qa[0][j], bh[t][0], bh[t][1]);
#pragma unroll
            for (int t = 0; t < 8; t++) mma(s[t], qa[1][j], bh[t][0], bh[t][1]);
        }

        // ---- online softmax ----
        float rx0 = -1e30f, rx1 = -1e30f;
#pragma unroll
        for (int t = 0; t < 8; t++) {
            rx0 = fmaxf(rx0, fmaxf(s[t][0], s[t][1]));
            rx1 = fmaxf(rx1, fmaxf(s[t][2], s[t][3]));
        }
        rx0 = fmaxf(rx0, __shfl_xor_sync(~0u, rx0, 1));
        rx0 = fmaxf(rx0, __shfl_xor_sync(~0u, rx0, 2));
        rx1 = fmaxf(rx1, __shfl_xor_sync(~0u, rx1, 1));
        rx1 = fmaxf(rx1, __shfl_xor_sync(~0u, rx1, 2));
        float mn0 = fmaxf(m0, rx0), mn1 = fmaxf(m1, rx1);
        float sc0 = ex2f((m0 - mn0) * L2E), sc1 = ex2f((m1 - mn1) * L2E);
        m0 = mn0; m1 = mn1;
        float rs0 = 0.f, rs1 = 0.f;
#pragma unroll
        for (int t = 0; t < 8; t++) {
            s[t][0] = ex2f((s[t][0] - mn0) * L2E);
            s[t][1] = ex2f((s[t][1] - mn0) * L2E);
            s[t][2] = ex2f((s[t][2] - mn1) * L2E);
            s[t][3] = ex2f((s[t][3] - mn1) * L2E);
            rs0 += s[t][0] + s[t][1];
            rs1 += s[t][2] + s[t][3];
        }
        rs0 += __shfl_xor_sync(~0u, rs0, 1); rs0 += __shfl_xor_sync(~0u, rs0, 2);
        rs1 += __shfl_xor_sync(~0u, rs1, 1); rs1 += __shfl_xor_sync(~0u, rs1, 2);
        l0 = l0 * sc0 + rs0; l1 = l1 * sc1 + rs1;
#pragma unroll
        for (int t = 0; t < 16; t++) {
            o[t][0] *= sc0; o[t][1] *= sc0; o[t][2] *= sc1; o[t][3] *= sc1;
        }

        uint32_t ph[4][4], pl[4][4];
#pragma unroll
        for (int j = 0; j < 4; j++) {
            pack2(s[2 * j][0],     s[2 * j][1],     ph[j][0], pl[j][0]);
            pack2(s[2 * j][2],     s[2 * j][3],     ph[j][1], pl[j][1]);
            pack2(s[2 * j + 1][0], s[2 * j + 1][1], ph[j][2], pl[j][2]);
            pack2(s[2 * j + 1][2], s[2 * j + 1][3], ph[j][3], pl[j][3]);
        }

        // ---- O += PhVh + PlVh — accumulator-interleaved sweeps ----
#pragma unroll
        for (int j = 0; j < 4; j++) {
            uint32_t vb[16][2];
#pragma unroll
            for (int t = 0; t < 16; t++) {
                int bi = (8 * t + lq) * 36 + j * 8 + lr;
                vb[t][0] = Vh32[bi]; vb[t][1] = Vh32[bi + 4];
            }
#pragma unroll
            for (int t = 0; t < 16; t++) mma(o[t], ph[j], vb[t][0], vb[t][1]);
#pragma unroll
            for (int t = 0; t < 16; t++) mma(o[t], pl[j], vb[t][0], vb[t][1]);
        }
    }

    float wm = W_m[h];
    float i0 = wm / l0, i1 = wm / l1;
    float* og = g_o + ((size_t)h * NT + q0 + w * 16) * D;
#pragma unroll
    for (int t = 0; t < 16; t++) {
        int col = 8 * t + lr * 2;
        *(float2*)(og + (size_t)lq * D + col)       = make_float2(o[t][0] * i0, o[t][1] * i0);
        *(float2*)(og + (size_t)(lq + 8) * D + col) = make_float2(o[t][2] * i1, o[t][3] * i1);
    }
}

// ================== prep: split x, split+transpose W ============================
__global__ void __launch_bounds__(256) splitx_kernel(const float* __restrict__ x) {
    int base = (blockIdx.x * 256 + threadIdx.x) * 8;
    float4 a = *(const float4*)(x + base);
    float4 b = *(const float4*)(x + base + 4);
    float v[8] = {a.x, a.y, a.z, a.w, b.x, b.y, b.z, b.w};
    __align__(16) __half hb[8], lb[8];
#pragma unroll
    for (int i = 0; i < 8; i++) {
        __half hh = __float2half_rn(v[i]);
        hb[i] = hh;
        lb[i] = __float2half_rn(v[i] - __half2float(hh));
    }
    *(uint4*)(g_xh + base) = *(uint4*)hb;
    *(uint4*)(g_xl + base) = *(uint4*)lb;
}

__global__ void __launch_bounds__(256) splitW_kernel(const float* __restrict__ Wk,
                                                     const float* __restrict__ Wq,
                                                     const float* __restrict__ Wv) {
    const int h = blockIdx.x, which = blockIdx.y;
    const float* W = (which == 0 ? Wq : which == 1 ? Wk : Wv) + (size_t)h * D * D;
    __half* oh = g_wT[which][0] + (size_t)h * D * D;
    __half* ol = g_wT[which][1] + (size_t)h * D * D;
    for (int idx = threadIdx.x; idx < D * D; idx += 256) {
        int dout = idx >> 7, f = idx & 127;
        float v = W[(size_t)f * D + dout];
        __half hh = __float2half_rn(v);
        oh[idx] = hh;
        ol[idx] = __float2half_rn(v - __half2float(hh));
    }
}

// ================== qkv via HMMA: grid (32, 8, 3), 256 threads ==================
#define WROW 136
#define QST  (128 * WROW * 2)
#define QSMEM (2 * QST)
#define TP 133

__global__ void __launch_bounds__(256) qkv_mma_kernel() {
    extern __shared__ char sm[];
    const int tid = threadIdx.x, w = tid >> 5, l = tid & 31;
    const int tile = blockIdx.x, h = blockIdx.y, which = blockIdx.z;
    const int lq = l >> 2, lr = l & 3;
    const int n0 = tile * 128;

    {
        const uint32_t sb = su32(sm);
        const __half* wh = g_wT[which][0] + (size_t)h * D * D;
        const __half* wl = g_wT[which][1] + (size_t)h * D * D;
        for (int c = tid; c < 2048; c += 256) {
            int r = c >> 4, k = c & 15;
            uint32_t so = (uint32_t)(r * (WROW * 2) + k * 16);
            CP16(sb + so,       wh + (size_t)r * D + k * 8);
            CP16(sb + QST + so, wl + (size_t)r * D + k * 8);
        }
        CPC();
    }

    uint32_t xa[2][8][4];
#pragma unroll
    for (int s = 0; s < 2; s++) {
        const __half* xs = (s ? g_xl : g_xh) + (size_t)(n0 + w * 16) * D;
#pragma unroll
        for (int j = 0; j < 8; j++) {
            const __half* base = xs + (size_t)lq * D + j * 16 + lr * 2;
            xa[s][j][0] = *(const uint32_t*)(base);
            xa[s][j][1] = *(const uint32_t*)(base + 8 * D);
            xa[s][j][2] = *(const uint32_t*)(base + 8);
            xa[s][j][3] = *(const uint32_t*)(base + 8 * D + 8);
        }
    }

    CPW0();
    __syncthreads();

    const uint32_t* Wh32 = (const uint32_t*)(sm);
    const uint32_t* Wl32 = (const uint32_t*)(sm + QST);

    float s[16][4];
#pragma unroll
    for (int t = 0; t < 16; t++) { s[t][0] = s[t][1] = s[t][2] = s[t][3] = 0.f; }
#pragma unroll
    for (int j = 0; j < 8; j++) {
#pragma unroll
        for (int t = 0; t < 16; t++) {
            int bi = (8 * t + lq) * (WROW / 2) + j * 8 + lr;
            mma(s[t], xa[0][j], Wh32[bi], Wh32[bi + 4]);
        }
#pragma unroll
        for (int t = 0; t < 16; t++) {
            int bi = (8 * t + lq) * (WROW / 2) + j * 8 + lr;
            mma(s[t], xa[1][j], Wh32[bi], Wh32[bi + 4]);
        }
#pragma unroll
        for (int t = 0; t < 16; t++) {
            int bi = (8 * t + lq) * (WROW / 2) + j * 8 + lr;
            mma(s[t], xa[0][j], Wl32[bi], Wl32[bi + 4]);
        }
    }

    if (which < 2) {
        // q: split hi/lo; k: hi only (Kl term dropped in attention)
        __half* oh = (which == 0 ? g_qh : g_kh) + ((size_t)h * NT + n0 + w * 16) * D;
#pragma unroll
        for (int t = 0; t < 16; t++) {
            int col = 8 * t + lr * 2;
            uint32_t h01, l01, h23, l23;
            pack2(s[t][0], s[t][1], h01, l01);
            pack2(s[t][2], s[t][3], h23, l23);
            *(uint32_t*)(oh + (size_t)lq * D + col)       = h01;
            *(uint32_t*)(oh + (size_t)(lq + 8) * D + col) = h23;
            if (which == 0) {
                __half* ol = g_ql + ((size_t)h * NT + n0 + w * 16) * D;
                *(uint32_t*)(ol + (size_t)lq * D + col)       = l01;
                *(uint32_t*)(ol + (size_t)(lq + 8) * D + col) = l23;
            }
        }
    } else {
        __syncthreads();
        float* buf = (float*)sm;
#pragma unroll
        for (int t = 0; t < 16; t++) {
            int c = 8 * t + lr * 2;
            int r0 = w * 16 + lq, r1 = r0 + 8;
            buf[r0 * TP + c] = s[t][0]; buf[r0 * TP + c + 1] = s[t][1];
            buf[r1 * TP + c] = s[t][2]; buf[r1 * TP + c + 1] = s[t][3];
        }
        __syncthreads();
#pragma unroll
        for (int dd = 0; dd < 16; dd++) {
            int d = w * 16 + dd;
            int n4 = l * 4;
            __align__(8) __half hb[4];
#pragma unroll
            for (int i = 0; i < 4; i++)
                hb[i] = __float2half_rn(buf[(n4 + i) * TP + d]);
            *(uint2*)(g_vh + ((size_t)h * D + d) * NT + n0 + n4) = *(uint2*)hb;
        }
    }
}

// ---------------- Wg transpose + final MLP --------------------------------------
__global__ void wgT_kernel(const float* __restrict__ Wg) {
    for (int it = threadIdx.x; it < D * D; it += blockDim.x) {
        int d = it >> 7, f = it & 127;
        g_wgT[f * D + d] = Wg[d * D + f];
    }
}

__global__ void __launch_bounds__(256) final_kernel(const float* __restrict__ x,
                                                    const float* __restrict__ bg,
                                                    float* __restrict__ y) {
    __shared__ float hs[64][D];
    __shared__ float Ws[16][D];
    __shared__ float bsh[D];
    const int n0 = blockIdx.x * 64;
    const int tid = threadIdx.x;

    for (int it = tid; it < 64 * 32; it += 256) {
        int r = it >> 5, c4 = it & 31;
        size_t off = (size_t)(n0 + r) * D + c4 * 4;
        float4 a = *(const float4*)(x + off);
#pragma unroll
        for (int hh = 0; hh < H; hh++) {
            float4 b = *(const float4*)(g_o + (size_t)hh * NT * D + off);
            a.x += b.x; a.y += b.y; a.z += b.z; a.w += b.w;
        }
        *(float4*)&hs[r][c4 * 4] = a;
    }
    if (tid < D) bsh[tid] = bg[tid];

    const int ty = tid >> 4, tx = tid & 15;
    float acc[4][8];
#pragma unroll
    for (int i = 0; i < 4; i++)
#pragma unroll
        for (int j = 0; j < 8; j++) acc[i][j] = 0.f;

    for (int fc = 0; fc < 8; fc++) {
        __syncthreads();
        for (int it = tid; it < 16 * 32; it += 256) {
            int r = it >> 5, c4 = it & 31;
            *(float4*)&Ws[r][c4 * 4] = *(const float4*)(g_wgT + (size_t)(fc * 16 + r) * D + c4 * 4);
        }
        __syncthreads();
#pragma unroll
        for (int f = 0; f < 16; f++) {
            float a[4];
#pragma unroll
            for (int ii = 0; ii < 4; ii++) a[ii] = hs[ty * 4 + ii][fc * 16 + f];
            float4 b0 = *(float4*)&Ws[f][tx * 8];
            float4 b1 = *(float4*)&Ws[f][tx * 8 + 4];
            float b[8] = {b0.x, b0.y, b0.z, b0.w, b1.x, b1.y, b1.z, b1.w};
#pragma unroll
            for (int ii = 0; ii < 4; ii++)
#pragma unroll
                for (int jj = 0; jj < 8; jj++)
                    acc[ii][jj] = fmaf(a[ii], b[jj], acc[ii][jj]);
        }
    }

#pragma unroll
    for (int ii = 0; ii < 4; ii++) {
        int n = n0 + ty * 4 + ii;
#pragma unroll
        for (int jj = 0; jj < 8; jj += 4) {
            int d = tx * 8 + jj;
            float4 xv = *(const float4*)(x + (size_t)n * D + d);
            float4 r;
            r.x = xv.x + fmaxf(acc[ii][jj + 0] + bsh[d + 0], 0.f);
            r.y = xv.y + fmaxf(acc[ii][jj + 1] + bsh[d + 1], 0.f);
            r.z = xv.z + fmaxf(acc[ii][jj + 2] + bsh[d + 2], 0.f);
            r.w = xv.w + fmaxf(acc[ii][jj + 3] + bsh[d + 3], 0.f);
            *(float4*)(y + (size_t)n * D + d) = r;
        }
    }
}

// ---------------- launch ---------------------------------------------------------
extern "C" void kernel_launch(void* const* d_in, const int* in_sizes, int n_in,
                              void* d_out, int out_size) {
    const float* x  = (const float*)d_in[0];
    const float* Wk = (const float*)d_in[1];
    const float* Wq = (const float*)d_in[2];
    const float* Wv = (const float*)d_in[3];
    const float* Wm = (const float*)d_in[4];
    const float* Wg = (const float*)d_in[5];
    const float* bg = (const float*)d_in[6];
    float* y = (float*)d_out;

    cudaFuncSetAttribute(attn_kernel, cudaFuncAttributeMaxDynamicSharedMemorySize, ASMEM);
    cudaFuncSetAttribute(qkv_mma_kernel, cudaFuncAttributeMaxDynamicSharedMemorySize, QSMEM);

    splitx_kernel<<<NT * D / (256 * 8), 256>>>(x);
    splitW_kernel<<<dim3(H, 3), 256>>>(Wk, Wq, Wv);
    qkv_mma_kernel<<<dim3(NT / 128, H, 3), 256, QSMEM>>>();
    attn_kernel<<<dim3(NT / 64, H), 128, ASMEM>>>(Wm);
    wgT_kernel<<<1, 256>>>(Wg);
    final_kernel<<<NT / 64, 256>>>(x, bg, y);
}

// round 12
// speedup vs baseline: 1.2551x; 1.0018x over previous
#include <cuda_runtime.h>
#include <cuda_fp16.h>
#include <cstdint>

#define NT 4096
#define D  128
#define H  8
#define BN 64
#define NB (NT / BN)
#define NTILES 512          // 64 q-tiles x 8 heads
#define PGRID 304           // 2 CTAs/SM x 152 SMs

// ---------------- scratch globals ---------------------------------------------
__device__ __align__(16) __half g_qh[H * NT * D];
__device__ __align__(16) __half g_ql[H * NT * D];
__device__ __align__(16) __half g_kh[H * NT * D];
__device__ __align__(16) __half g_vh[H * D * NT];   // transposed [h][d][n]
__device__ __align__(16) float  g_o[H * NT * D];
__device__ float g_wgT[D * D];
__device__ unsigned int g_ctr;

__device__ __align__(16) __half g_xh[NT * D];
__device__ __align__(16) __half g_xl[NT * D];
__device__ __align__(16) __half g_wT[3][2][H * D * D];   // [which][hi/lo][h][dout][f]

// ---------------- helpers -------------------------------------------------------
__device__ __forceinline__ float ex2f(float x) {
    float y; asm("ex2.approx.ftz.f32 %0,%1;" : "=f"(y) : "f"(x)); return y;
}
#define CP16(d, s) asm volatile("cp.async.cg.shared.global [%0],[%1],16;" :: "r"(d), "l"(s) : "memory")
#define CPC()  asm volatile("cp.async.commit_group;" ::: "memory")
#define CPW0() asm volatile("cp.async.wait_group 0;" ::: "memory")
#define CPW1() asm volatile("cp.async.wait_group 1;" ::: "memory")

__device__ __forceinline__ uint32_t su32(const void* p) {
    return (uint32_t)__cvta_generic_to_shared(p);
}

__device__ __forceinline__ void mma(float* c, const uint32_t* a, uint32_t b0, uint32_t b1) {
    asm volatile(
        "mma.sync.aligned.m16n8k16.row.col.f32.f16.f16.f32 "
        "{%0,%1,%2,%3},{%4,%5,%6,%7},{%8,%9},{%0,%1,%2,%3};"
        : "+f"(c[0]), "+f"(c[1]), "+f"(c[2]), "+f"(c[3])
        : "r"(a[0]), "r"(a[1]), "r"(a[2]), "r"(a[3]), "r"(b0), "r"(b1));
}

__device__ __forceinline__ void pack2(float a, float b, uint32_t& hi, uint32_t& lo) {
    __half2 h = __floats2half2_rn(a, b);
    float2 f = __half22float2(h);
    __half2 r = __floats2half2_rn(a - f.x, b - f.y);
    hi = *(uint32_t*)&h; lo = *(uint32_t*)&r;
}

// ================== attention smem (per CTA; 2 CTAs/SM) =========================
// K stages x2: Kh[64][136] ; V stages x2: [128][72]
#define KST    17408
#define OFF_V  (2 * KST)                // 34816
#define VST    18432
#define ASMEM  (OFF_V + 2 * VST)        // 71680

__device__ __forceinline__ void load_stage(uint32_t sb, int h, int kb, int tid) {
    size_t kof = (size_t)h * NT * D + (size_t)kb * BN * D;
    size_t vof = (size_t)h * D * NT + (size_t)kb * BN;
    uint32_t kbase = sb + (uint32_t)(kb & 1) * KST;
    uint32_t vbase = sb + OFF_V + (uint32_t)(kb & 1) * VST;
    for (int c = tid; c < 1024; c += 128) {          // Kh: 64 rows x 16 chunks
        int r = c >> 4, k = c & 15;
        CP16(kbase + (uint32_t)(r * 272 + k * 16), g_kh + kof + (size_t)r * D + k * 8);
    }
    for (int c = tid; c < 1024; c += 128) {          // V: 128 dim-rows x 8 chunks
        int r = c >> 3, k = c & 7;
        CP16(vbase + (uint32_t)(r * 144 + k * 16), g_vh + vof + (size_t)r * NT + k * 8);
    }
}

__global__ void reset_ctr_kernel() { g_ctr = 0u; }

// ---------------- attention: persistent, grid 304, 128 threads, 2 CTAs/SM -------
__global__ void __launch_bounds__(128, 2) attn_kernel(const float* __restrict__ W_m) {
    extern __shared__ char sm[];
    __shared__ unsigned int sidx;
    const int tid = threadIdx.x, w = tid >> 5, l = tid & 31;
    const int lq = l >> 2, lr = l & 3;
    const uint32_t sb = su32(sm);
    const float L2E = 1.4426950408889634f;

    while (true) {
        if (tid == 0) sidx = atomicAdd(&g_ctr, 1u);
        __syncthreads();
        const unsigned int idx = sidx;
        if (idx >= NTILES) break;
        const int h = (int)(idx >> 6);          // same head for consecutive items
        const int q0 = (int)(idx & 63) * 64;

        // Q fragments hi/lo (regs)
        uint32_t qa[2][8][4];
#pragma unroll
        for (int s = 0; s < 2; s++) {
            const __half* qs = (s ? g_ql : g_qh) + ((size_t)h * NT + q0 + w * 16) * D;
#pragma unroll
            for (int j = 0; j < 8; j++) {
                const __half* base = qs + (size_t)lq * D + j * 16 + lr * 2;
                qa[s][j][0] = *(const uint32_t*)(base);
                qa[s][j][1] = *(const uint32_t*)(base + 8 * D);
                qa[s][j][2] = *(const uint32_t*)(base + 8);
                qa[s][j][3] = *(const uint32_t*)(base + 8 * D + 8);
            }
        }

        load_stage(sb, h, 0, tid); CPC();

        float o[16][4];
#pragma unroll
        for (int t = 0; t < 16; t++) { o[t][0] = o[t][1] = o[t][2] = o[t][3] = 0.f; }
        float m0 = -1e30f, m1 = -1e30f, l0 = 0.f, l1 = 0.f;

        for (int kb = 0; kb < NB; kb++) {
            __syncthreads();
            if (kb + 1 < NB) load_stage(sb, h, kb + 1, tid);
            CPC(); CPW1();
            __syncthreads();

            const uint32_t* Kh32 = (const uint32_t*)(sm + (kb & 1) * KST);
            const uint32_t* Vh32 = (const uint32_t*)(sm + OFF_V + (kb & 1) * VST);

            // ---- S = QhKh + QlKh — accumulator-interleaved sweeps ----
            float s[8][4];
#pragma unroll
            for (int t = 0; t < 8; t++) { s[t][0] = s[t][1] = s[t][2] = s[t][3] = 0.f; }
#pragma unroll
            for (int j = 0; j < 8; j++) {
                uint32_t bh[8][2];
#pragma unroll
                for (int t = 0; t < 8; t++) {
                    int bi = (8 * t + lq) * 68 + j * 8 + lr;
                    bh[t][0] = Kh32[bi]; bh[t][1] = Kh32[bi + 4];
                }
#pragma unroll
                for (int t = 0; t < 8; t++) mma(s[t], qa[0][j], bh[t][0], bh[t][1]);
#pragma unroll
                for (int t = 0; t < 8; t++) mma(s[t], qa[1][j], bh[t][0], bh[t][1]);
            }

            // ---- online softmax ----
            float rx0 = -1e30f, rx1 = -1e30f;
#pragma unroll
            for (int t = 0; t < 8; t++) {
                rx0 = fmaxf(rx0, fmaxf(s[t][0], s[t][1]));
                rx1 = fmaxf(rx1, fmaxf(s[t][2], s[t][3]));
            }
            rx0 = fmaxf(rx0, __shfl_xor_sync(~0u, rx0, 1));
            rx0 = fmaxf(rx0, __shfl_xor_sync(~0u, rx0, 2));
            rx1 = fmaxf(rx1, __shfl_xor_sync(~0u, rx1, 1));
            rx1 = fmaxf(rx1, __shfl_xor_sync(~0u, rx1, 2));
            float mn0 = fmaxf(m0, rx0), mn1 = fmaxf(m1, rx1);
            float sc0 = ex2f((m0 - mn0) * L2E), sc1 = ex2f((m1 - mn1) * L2E);
            m0 = mn0; m1 = mn1;
            float rs0 = 0.f, rs1 = 0.f;
#pragma unroll
            for (int t = 0; t < 8; t++) {
                s[t][0] = ex2f((s[t][0] - mn0) * L2E);
                s[t][1] = ex2f((s[t][1] - mn0) * L2E);
                s[t][2] = ex2f((s[t][2] - mn1) * L2E);
                s[t][3] = ex2f((s[t][3] - mn1) * L2E);
                rs0 += s[t][0] + s[t][1];
                rs1 += s[t][2] + s[t][3];
            }
            rs0 += __shfl_xor_sync(~0u, rs0, 1); rs0 += __shfl_xor_sync(~0u, rs0, 2);
            rs1 += __shfl_xor_sync(~0u, rs1, 1); rs1 += __shfl_xor_sync(~0u, rs1, 2);
            l0 = l0 * sc0 + rs0; l1 = l1 * sc1 + rs1;
#pragma unroll
            for (int t = 0; t < 16; t++) {
                o[t][0] *= sc0; o[t][1] *= sc0; o[t][2] *= sc1; o[t][3] *= sc1;
            }

            uint32_t ph[4][4], pl[4][4];
#pragma unroll
            for (int j = 0; j < 4; j++) {
                pack2(s[2 * j][0],     s[2 * j][1],     ph[j][0], pl[j][0]);
                pack2(s[2 * j][2],     s[2 * j][3],     ph[j][1], pl[j][1]);
                pack2(s[2 * j + 1][0], s[2 * j + 1][1], ph[j][2], pl[j][2]);
                pack2(s[2 * j + 1][2], s[2 * j + 1][3], ph[j][3], pl[j][3]);
            }

            // ---- O += PhVh + PlVh — accumulator-interleaved sweeps ----
#pragma unroll
            for (int j = 0; j < 4; j++) {
                uint32_t vb[16][2];
#pragma unroll
                for (int t = 0; t < 16; t++) {
                    int bi = (8 * t + lq) * 36 + j * 8 + lr;
                    vb[t][0] = Vh32[bi]; vb[t][1] = Vh32[bi + 4];
                }
#pragma unroll
                for (int t = 0; t < 16; t++) mma(o[t], ph[j], vb[t][0], vb[t][1]);
#pragma unroll
                for (int t = 0; t < 16; t++) mma(o[t], pl[j], vb[t][0], vb[t][1]);
            }
        }

        float wm = W_m[h];
        float i0 = wm / l0, i1 = wm / l1;
        float* og = g_o + ((size_t)h * NT + q0 + w * 16) * D;
#pragma unroll
        for (int t = 0; t < 16; t++) {
            int col = 8 * t + lr * 2;
            *(float2*)(og + (size_t)lq * D + col)       = make_float2(o[t][0] * i0, o[t][1] * i0);
            *(float2*)(og + (size_t)(lq + 8) * D + col) = make_float2(o[t][2] * i1, o[t][3] * i1);
        }
        __syncthreads();   // all reads of sidx / smem done before next item
    }
}

// ================== prep: split x, split+transpose W ============================
__global__ void __launch_bounds__(256) splitx_kernel(const float* __restrict__ x) {
    int base = (blockIdx.x * 256 + threadIdx.x) * 8;
    float4 a = *(const float4*)(x + base);
    float4 b = *(const float4*)(x + base + 4);
    float v[8] = {a.x, a.y, a.z, a.w, b.x, b.y, b.z, b.w};
    __align__(16) __half hb[8], lb[8];
#pragma unroll
    for (int i = 0; i < 8; i++) {
        __half hh = __float2half_rn(v[i]);
        hb[i] = hh;
        lb[i] = __float2half_rn(v[i] - __half2float(hh));
    }
    *(uint4*)(g_xh + base) = *(uint4*)hb;
    *(uint4*)(g_xl + base) = *(uint4*)lb;
}

__global__ void __launch_bounds__(256) splitW_kernel(const float* __restrict__ Wk,
                                                     const float* __restrict__ Wq,
                                                     const float* __restrict__ Wv) {
    const int h = blockIdx.x, which = blockIdx.y;
    const float* W = (which == 0 ? Wq : which == 1 ? Wk : Wv) + (size_t)h * D * D;
    __half* oh = g_wT[which][0] + (size_t)h * D * D;
    __half* ol = g_wT[which][1] + (size_t)h * D * D;
    for (int idx = threadIdx.x; idx < D * D; idx += 256) {
        int dout = idx >> 7, f = idx & 127;
        float v = W[(size_t)f * D + dout];
        __half hh = __float2half_rn(v);
        oh[idx] = hh;
        ol[idx] = __float2half_rn(v - __half2float(hh));
    }
}

// ================== qkv via HMMA: grid (32, 8, 3), 256 threads ==================
#define WROW 136
#define QST  (128 * WROW * 2)
#define QSMEM (2 * QST)
#define TP 133

__global__ void __launch_bounds__(256) qkv_mma_kernel() {
    extern __shared__ char sm[];
    const int tid = threadIdx.x, w = tid >> 5, l = tid & 31;
    const int tile = blockIdx.x, h = blockIdx.y, which = blockIdx.z;
    const int lq = l >> 2, lr = l & 3;
    const int n0 = tile * 128;

    {
        const uint32_t sb = su32(sm);
        const __half* wh = g_wT[which][0] + (size_t)h * D * D;
        const __half* wl = g_wT[which][1] + (size_t)h * D * D;
        for (int c = tid; c < 2048; c += 256) {
            int r = c >> 4, k = c & 15;
            uint32_t so = (uint32_t)(r * (WROW * 2) + k * 16);
            CP16(sb + so,       wh + (size_t)r * D + k * 8);
            CP16(sb + QST + so, wl + (size_t)r * D + k * 8);
        }
        CPC();
    }

    uint32_t xa[2][8][4];
#pragma unroll
    for (int s = 0; s < 2; s++) {
        const __half* xs = (s ? g_xl : g_xh) + (size_t)(n0 + w * 16) * D;
#pragma unroll
        for (int j = 0; j < 8; j++) {
            const __half* base = xs + (size_t)lq * D + j * 16 + lr * 2;
            xa[s][j][0] = *(const uint32_t*)(base);
            xa[s][j][1] = *(const uint32_t*)(base + 8 * D);
            xa[s][j][2] = *(const uint32_t*)(base + 8);
            xa[s][j][3] = *(const uint32_t*)(base + 8 * D + 8);
        }
    }

    CPW0();
    __syncthreads();

    const uint32_t* Wh32 = (const uint32_t*)(sm);
    const uint32_t* Wl32 = (const uint32_t*)(sm + QST);

    float s[16][4];
#pragma unroll
    for (int t = 0; t < 16; t++) { s[t][0] = s[t][1] = s[t][2] = s[t][3] = 0.f; }
#pragma unroll
    for (int j = 0; j < 8; j++) {
#pragma unroll
        for (int t = 0; t < 16; t++) {
            int bi = (8 * t + lq) * (WROW / 2) + j * 8 + lr;
            mma(s[t], xa[0][j], Wh32[bi], Wh32[bi + 4]);
        }
#pragma unroll
        for (int t = 0; t < 16; t++) {
            int bi = (8 * t + lq) * (WROW / 2) + j * 8 + lr;
            mma(s[t], xa[1][j], Wh32[bi], Wh32[bi + 4]);
        }
#pragma unroll
        for (int t = 0; t < 16; t++) {
            int bi = (8 * t + lq) * (WROW / 2) + j * 8 + lr;
            mma(s[t], xa[0][j], Wl32[bi], Wl32[bi + 4]);
        }
    }

    if (which < 2) {
        // q: split hi/lo; k: hi only (Kl term dropped in attention)
        __half* oh = (which == 0 ? g_qh : g_kh) + ((size_t)h * NT + n0 + w * 16) * D;
#pragma unroll
        for (int t = 0; t < 16; t++) {
            int col = 8 * t + lr * 2;
            uint32_t h01, l01, h23, l23;
            pack2(s[t][0], s[t][1], h01, l01);
            pack2(s[t][2], s[t][3], h23, l23);
            *(uint32_t*)(oh + (size_t)lq * D + col)       = h01;
            *(uint32_t*)(oh + (size_t)(lq + 8) * D + col) = h23;
            if (which == 0) {
                __half* ol = g_ql + ((size_t)h * NT + n0 + w * 16) * D;
                *(uint32_t*)(ol + (size_t)lq * D + col)       = l01;
                *(uint32_t*)(ol + (size_t)(lq + 8) * D + col) = l23;
            }
        }
    } else {
        __syncthreads();
        float* buf = (float*)sm;
#pragma unroll
        for (int t = 0; t < 16; t++) {
            int c = 8 * t + lr * 2;
            int r0 = w * 16 + lq, r1 = r0 + 8;
            buf[r0 * TP + c] = s[t][0]; buf[r0 * TP + c + 1] = s[t][1];
            buf[r1 * TP + c] = s[t][2]; buf[r1 * TP + c + 1] = s[t][3];
        }
        __syncthreads();
#pragma unroll
        for (int dd = 0; dd < 16; dd++) {
            int d = w * 16 + dd;
            int n4 = l * 4;
            __align__(8) __half hb[4];
#pragma unroll
            for (int i = 0; i < 4; i++)
                hb[i] = __float2half_rn(buf[(n4 + i) * TP + d]);
            *(uint2*)(g_vh + ((size_t)h * D + d) * NT + n0 + n4) = *(uint2*)hb;
        }
    }
}

// ---------------- Wg transpose + final MLP --------------------------------------
__global__ void wgT_kernel(const float* __restrict__ Wg) {
    for (int it = threadIdx.x; it < D * D; it += blockDim.x) {
        int d = it >> 7, f = it & 127;
        g_wgT[f * D + d] = Wg[d * D + f];
    }
}

__global__ void __launch_bounds__(256) final_kernel(const float* __restrict__ x,
                                                    const float* __restrict__ bg,
                                                    float* __restrict__ y) {
    __shared__ float hs[64][D];
    __shared__ float Ws[16][D];
    __shared__ float bsh[D];
    const int n0 = blockIdx.x * 64;
    const int tid = threadIdx.x;

    for (int it = tid; it < 64 * 32; it += 256) {
        int r = it >> 5, c4 = it & 31;
        size_t off = (size_t)(n0 + r) * D + c4 * 4;
        float4 a = *(const float4*)(x + off);
#pragma unroll
        for (int hh = 0; hh < H; hh++) {
            float4 b = *(const float4*)(g_o + (size_t)hh * NT * D + off);
            a.x += b.x; a.y += b.y; a.z += b.z; a.w += b.w;
        }
        *(float4*)&hs[r][c4 * 4] = a;
    }
    if (tid < D) bsh[tid] = bg[tid];

    const int ty = tid >> 4, tx = tid & 15;
    float acc[4][8];
#pragma unroll
    for (int i = 0; i < 4; i++)
#pragma unroll
        for (int j = 0; j < 8; j++) acc[i][j] = 0.f;

    for (int fc = 0; fc < 8; fc++) {
        __syncthreads();
        for (int it = tid; it < 16 * 32; it += 256) {
            int r = it >> 5, c4 = it & 31;
            *(float4*)&Ws[r][c4 * 4] = *(const float4*)(g_wgT + (size_t)(fc * 16 + r) * D + c4 * 4);
        }
        __syncthreads();
#pragma unroll
        for (int f = 0; f < 16; f++) {
            float a[4];
#pragma unroll
            for (int ii = 0; ii < 4; ii++) a[ii] = hs[ty * 4 + ii][fc * 16 + f];
            float4 b0 = *(float4*)&Ws[f][tx * 8];
            float4 b1 = *(float4*)&Ws[f][tx * 8 + 4];
            float b[8] = {b0.x, b0.y, b0.z, b0.w, b1.x, b1.y, b1.z, b1.w};
#pragma unroll
            for (int ii = 0; ii < 4; ii++)
#pragma unroll
                for (int jj = 0; jj < 8; jj++)
                    acc[ii][jj] = fmaf(a[ii], b[jj], acc[ii][jj]);
        }
    }

#pragma unroll
    for (int ii = 0; ii < 4; ii++) {
        int n = n0 + ty * 4 + ii;
#pragma unroll
        for (int jj = 0; jj < 8; jj += 4) {
            int d = tx * 8 + jj;
            float4 xv = *(const float4*)(x + (size_t)n * D + d);
            float4 r;
            r.x = xv.x + fmaxf(acc[ii][jj + 0] + bsh[d + 0], 0.f);
            r.y = xv.y + fmaxf(acc[ii][jj + 1] + bsh[d + 1], 0.f);
            r.z = xv.z + fmaxf(acc[ii][jj + 2] + bsh[d + 2], 0.f);
            r.w = xv.w + fmaxf(acc[ii][jj + 3] + bsh[d + 3], 0.f);
            *(float4*)(y + (size_t)n * D + d) = r;
        }
    }
}

// ---------------- launch ---------------------------------------------------------
extern "C" void kernel_launch(void* const* d_in, const int* in_sizes, int n_in,
                              void* d_out, int out_size) {
    const float* x  = (const float*)d_in[0];
    const float* Wk = (const float*)d_in[1];
    const float* Wq = (const float*)d_in[2];
    const float* Wv = (const float*)d_in[3];
    const float* Wm = (const float*)d_in[4];
    const float* Wg = (const float*)d_in[5];
    const float* bg = (const float*)d_in[6];
    float* y = (float*)d_out;

    cudaFuncSetAttribute(attn_kernel, cudaFuncAttributeMaxDynamicSharedMemorySize, ASMEM);
    cudaFuncSetAttribute(qkv_mma_kernel, cudaFuncAttributeMaxDynamicSharedMemorySize, QSMEM);

    reset_ctr_kernel<<<1, 1>>>();
    splitx_kernel<<<NT * D / (256 * 8), 256>>>(x);
    splitW_kernel<<<dim3(H, 3), 256>>>(Wk, Wq, Wv);
    qkv_mma_kernel<<<dim3(NT / 128, H, 3), 256, QSMEM>>>();
    attn_kernel<<<PGRID, 128, ASMEM>>>(Wm);
    wgT_kernel<<<1, 256>>>(Wg);
    final_kernel<<<NT / 64, 256>>>(x, bg, y);
}

// round 13
// speedup vs baseline: 1.3643x; 1.0870x over previous
#include <cuda_runtime.h>
#include <cuda_fp16.h>
#include <cstdint>

#define NT 4096
#define D  128
#define H  8
#define BN 64
#define NB (NT / BN)
#define NTILES 512          // 64 q-tiles x 8 heads
#define PGRID 304           // 2 CTAs/SM x 152 SMs

// ---------------- scratch globals ---------------------------------------------
__device__ __align__(16) __half g_qh[H * NT * D];
__device__ __align__(16) __half g_ql[H * NT * D];
__device__ __align__(16) __half g_kh[H * NT * D];
__device__ __align__(16) __half g_vh[H * D * NT];   // transposed [h][d][n]
__device__ __align__(16) float  g_o[H * NT * D];
__device__ float g_wgT[D * D];
__device__ unsigned int g_ctr;

__device__ __align__(16) __half g_xh[NT * D];
__device__ __align__(16) __half g_xl[NT * D];
__device__ __align__(16) __half g_wT[3][2][H * D * D];   // [which][hi/lo][h][dout][f]

// ---------------- helpers -------------------------------------------------------
__device__ __forceinline__ float ex2f(float x) {
    float y; asm("ex2.approx.ftz.f32 %0,%1;" : "=f"(y) : "f"(x)); return y;
}
#define CP16(d, s) asm volatile("cp.async.cg.shared.global [%0],[%1],16;" :: "r"(d), "l"(s) : "memory")
#define CPC()  asm volatile("cp.async.commit_group;" ::: "memory")
#define CPW0() asm volatile("cp.async.wait_group 0;" ::: "memory")
#define CPW1() asm volatile("cp.async.wait_group 1;" ::: "memory")

__device__ __forceinline__ uint32_t su32(const void* p) {
    return (uint32_t)__cvta_generic_to_shared(p);
}

__device__ __forceinline__ void mma(float* c, const uint32_t* a, uint32_t b0, uint32_t b1) {
    asm volatile(
        "mma.sync.aligned.m16n8k16.row.col.f32.f16.f16.f32 "
        "{%0,%1,%2,%3},{%4,%5,%6,%7},{%8,%9},{%0,%1,%2,%3};"
        : "+f"(c[0]), "+f"(c[1]), "+f"(c[2]), "+f"(c[3])
        : "r"(a[0]), "r"(a[1]), "r"(a[2]), "r"(a[3]), "r"(b0), "r"(b1));
}

__device__ __forceinline__ void pack2(float a, float b, uint32_t& hi, uint32_t& lo) {
    __half2 h = __floats2half2_rn(a, b);
    float2 f = __half22float2(h);
    __half2 r = __floats2half2_rn(a - f.x, b - f.y);
    hi = *(uint32_t*)&h; lo = *(uint32_t*)&r;
}

// pack to fp16 pair AND return the rounded-value sum (for consistent l)
__device__ __forceinline__ uint32_t packsum(float a, float b, float& acc) {
    __half2 h = __floats2half2_rn(a, b);
    float2 f = __half22float2(h);
    acc += f.x + f.y;
    return *(uint32_t*)&h;
}

// ================== attention smem (per CTA; 2 CTAs/SM) =========================
// K stages x2: Kh[64][136] ; V stages x2: [128][72]
#define KST    17408
#define OFF_V  (2 * KST)                // 34816
#define VST    18432
#define ASMEM  (OFF_V + 2 * VST)        // 71680

__device__ __forceinline__ void load_stage(uint32_t sb, int h, int kb, int tid) {
    size_t kof = (size_t)h * NT * D + (size_t)kb * BN * D;
    size_t vof = (size_t)h * D * NT + (size_t)kb * BN;
    uint32_t kbase = sb + (uint32_t)(kb & 1) * KST;
    uint32_t vbase = sb + OFF_V + (uint32_t)(kb & 1) * VST;
    for (int c = tid; c < 1024; c += 128) {          // Kh: 64 rows x 16 chunks
        int r = c >> 4, k = c & 15;
        CP16(kbase + (uint32_t)(r * 272 + k * 16), g_kh + kof + (size_t)r * D + k * 8);
    }
    for (int c = tid; c < 1024; c += 128) {          // V: 128 dim-rows x 8 chunks
        int r = c >> 3, k = c & 7;
        CP16(vbase + (uint32_t)(r * 144 + k * 16), g_vh + vof + (size_t)r * NT + k * 8);
    }
}

__global__ void reset_ctr_kernel() { g_ctr = 0u; }

// ---------------- attention: persistent, grid 304, 128 threads, 2 CTAs/SM -------
__global__ void __launch_bounds__(128, 2) attn_kernel(const float* __restrict__ W_m) {
    extern __shared__ char sm[];
    __shared__ unsigned int sidx;
    const int tid = threadIdx.x, w = tid >> 5, l = tid & 31;
    const int lq = l >> 2, lr = l & 3;
    const uint32_t sb = su32(sm);
    const float L2E = 1.4426950408889634f;

    while (true) {
        if (tid == 0) sidx = atomicAdd(&g_ctr, 1u);
        __syncthreads();
        const unsigned int idx = sidx;
        if (idx >= NTILES) break;
        const int h = (int)(idx >> 6);
        const int q0 = (int)(idx & 63) * 64;

        // Q fragments hi/lo (regs)
        uint32_t qa[2][8][4];
#pragma unroll
        for (int s = 0; s < 2; s++) {
            const __half* qs = (s ? g_ql : g_qh) + ((size_t)h * NT + q0 + w * 16) * D;
#pragma unroll
            for (int j = 0; j < 8; j++) {
                const __half* base = qs + (size_t)lq * D + j * 16 + lr * 2;
                qa[s][j][0] = *(const uint32_t*)(base);
                qa[s][j][1] = *(const uint32_t*)(base + 8 * D);
                qa[s][j][2] = *(const uint32_t*)(base + 8);
                qa[s][j][3] = *(const uint32_t*)(base + 8 * D + 8);
            }
        }

        load_stage(sb, h, 0, tid); CPC();

        float o[16][4];
#pragma unroll
        for (int t = 0; t < 16; t++) { o[t][0] = o[t][1] = o[t][2] = o[t][3] = 0.f; }
        float m0 = -1e30f, m1 = -1e30f, l0 = 0.f, l1 = 0.f;

        for (int kb = 0; kb < NB; kb++) {
            __syncthreads();
            if (kb + 1 < NB) load_stage(sb, h, kb + 1, tid);
            CPC(); CPW1();
            __syncthreads();

            const uint32_t* Kh32 = (const uint32_t*)(sm + (kb & 1) * KST);
            const uint32_t* Vh32 = (const uint32_t*)(sm + OFF_V + (kb & 1) * VST);

            // ---- S = QhKh + QlKh — accumulator-interleaved sweeps ----
            float s[8][4];
#pragma unroll
            for (int t = 0; t < 8; t++) { s[t][0] = s[t][1] = s[t][2] = s[t][3] = 0.f; }
#pragma unroll
            for (int j = 0; j < 8; j++) {
                uint32_t bh[8][2];
#pragma unroll
                for (int t = 0; t < 8; t++) {
                    int bi = (8 * t + lq) * 68 + j * 8 + lr;
                    bh[t][0] = Kh32[bi]; bh[t][1] = Kh32[bi + 4];
                }
#pragma unroll
                for (int t = 0; t < 8; t++) mma(s[t], qa[0][j], bh[t][0], bh[t][1]);
#pragma unroll
                for (int t = 0; t < 8; t++) mma(s[t], qa[1][j], bh[t][0], bh[t][1]);
            }

            // ---- online softmax ----
            float rx0 = -1e30f, rx1 = -1e30f;
#pragma unroll
            for (int t = 0; t < 8; t++) {
                rx0 = fmaxf(rx0, fmaxf(s[t][0], s[t][1]));
                rx1 = fmaxf(rx1, fmaxf(s[t][2], s[t][3]));
            }
            rx0 = fmaxf(rx0, __shfl_xor_sync(~0u, rx0, 1));
            rx0 = fmaxf(rx0, __shfl_xor_sync(~0u, rx0, 2));
            rx1 = fmaxf(rx1, __shfl_xor_sync(~0u, rx1, 1));
            rx1 = fmaxf(rx1, __shfl_xor_sync(~0u, rx1, 2));
            float mn0 = fmaxf(m0, rx0), mn1 = fmaxf(m1, rx1);
            float sc0 = ex2f((m0 - mn0) * L2E), sc1 = ex2f((m1 - mn1) * L2E);
            m0 = mn0; m1 = mn1;
#pragma unroll
            for (int t = 0; t < 8; t++) {
                s[t][0] = ex2f((s[t][0] - mn0) * L2E);
                s[t][1] = ex2f((s[t][1] - mn0) * L2E);
                s[t][2] = ex2f((s[t][2] - mn1) * L2E);
                s[t][3] = ex2f((s[t][3] - mn1) * L2E);
            }

            // ---- pack P (fp16 only) and sum the ROUNDED values for l ----
            float rs0 = 0.f, rs1 = 0.f;
            uint32_t ph[4][4];
#pragma unroll
            for (int j = 0; j < 4; j++) {
                ph[j][0] = packsum(s[2 * j][0],     s[2 * j][1],     rs0);
                ph[j][1] = packsum(s[2 * j][2],     s[2 * j][3],     rs1);
                ph[j][2] = packsum(s[2 * j + 1][0], s[2 * j + 1][1], rs0);
                ph[j][3] = packsum(s[2 * j + 1][2], s[2 * j + 1][3], rs1);
            }
            rs0 += __shfl_xor_sync(~0u, rs0, 1); rs0 += __shfl_xor_sync(~0u, rs0, 2);
            rs1 += __shfl_xor_sync(~0u, rs1, 1); rs1 += __shfl_xor_sync(~0u, rs1, 2);
            l0 = l0 * sc0 + rs0; l1 = l1 * sc1 + rs1;
#pragma unroll
            for (int t = 0; t < 16; t++) {
                o[t][0] *= sc0; o[t][1] *= sc0; o[t][2] *= sc1; o[t][3] *= sc1;
            }

            // ---- O += PhVh — accumulator-interleaved sweep (single term) ----
#pragma unroll
            for (int j = 0; j < 4; j++) {
                uint32_t vb[16][2];
#pragma unroll
                for (int t = 0; t < 16; t++) {
                    int bi = (8 * t + lq) * 36 + j * 8 + lr;
                    vb[t][0] = Vh32[bi]; vb[t][1] = Vh32[bi + 4];
                }
#pragma unroll
                for (int t = 0; t < 16; t++) mma(o[t], ph[j], vb[t][0], vb[t][1]);
            }
        }

        float wm = W_m[h];
        float i0 = wm / l0, i1 = wm / l1;
        float* og = g_o + ((size_t)h * NT + q0 + w * 16) * D;
#pragma unroll
        for (int t = 0; t < 16; t++) {
            int col = 8 * t + lr * 2;
            *(float2*)(og + (size_t)lq * D + col)       = make_float2(o[t][0] * i0, o[t][1] * i0);
            *(float2*)(og + (size_t)(lq + 8) * D + col) = make_float2(o[t][2] * i1, o[t][3] * i1);
        }
        __syncthreads();   // all reads of sidx / smem done before next item
    }
}

// ================== prep: split x, split+transpose W ============================
__global__ void __launch_bounds__(256) splitx_kernel(const float* __restrict__ x) {
    int base = (blockIdx.x * 256 + threadIdx.x) * 8;
    float4 a = *(const float4*)(x + base);
    float4 b = *(const float4*)(x + base + 4);
    float v[8] = {a.x, a.y, a.z, a.w, b.x, b.y, b.z, b.w};
    __align__(16) __half hb[8], lb[8];
#pragma unroll
    for (int i = 0; i < 8; i++) {
        __half hh = __float2half_rn(v[i]);
        hb[i] = hh;
        lb[i] = __float2half_rn(v[i] - __half2float(hh));
    }
    *(uint4*)(g_xh + base) = *(uint4*)hb;
    *(uint4*)(g_xl + base) = *(uint4*)lb;
}

__global__ void __launch_bounds__(256) splitW_kernel(const float* __restrict__ Wk,
                                                     const float* __restrict__ Wq,
                                                     const float* __restrict__ Wv) {
    const int h = blockIdx.x, which = blockIdx.y;
    const float* W = (which == 0 ? Wq : which == 1 ? Wk : Wv) + (size_t)h * D * D;
    __half* oh = g_wT[which][0] + (size_t)h * D * D;
    __half* ol = g_wT[which][1] + (size_t)h * D * D;
    for (int idx = threadIdx.x; idx < D * D; idx += 256) {
        int dout = idx >> 7, f = idx & 127;
        float v = W[(size_t)f * D + dout];
        __half hh = __float2half_rn(v);
        oh[idx] = hh;
        ol[idx] = __float2half_rn(v - __half2float(hh));
    }
}

// ================== qkv via HMMA: grid (32, 8, 3), 256 threads ==================
#define WROW 136
#define QST  (128 * WROW * 2)
#define QSMEM (2 * QST)
#define TP 133

__global__ void __launch_bounds__(256) qkv_mma_kernel() {
    extern __shared__ char sm[];
    const int tid = threadIdx.x, w = tid >> 5, l = tid & 31;
    const int tile = blockIdx.x, h = blockIdx.y, which = blockIdx.z;
    const int lq = l >> 2, lr = l & 3;
    const int n0 = tile * 128;

    {
        const uint32_t sb = su32(sm);
        const __half* wh = g_wT[which][0] + (size_t)h * D * D;
        const __half* wl = g_wT[which][1] + (size_t)h * D * D;
        for (int c = tid; c < 2048; c += 256) {
            int r = c >> 4, k = c & 15;
            uint32_t so = (uint32_t)(r * (WROW * 2) + k * 16);
            CP16(sb + so,       wh + (size_t)r * D + k * 8);
            CP16(sb + QST + so, wl + (size_t)r * D + k * 8);
        }
        CPC();
    }

    uint32_t xa[2][8][4];
#pragma unroll
    for (int s = 0; s < 2; s++) {
        const __half* xs = (s ? g_xl : g_xh) + (size_t)(n0 + w * 16) * D;
#pragma unroll
        for (int j = 0; j < 8; j++) {
            const __half* base = xs + (size_t)lq * D + j * 16 + lr * 2;
            xa[s][j][0] = *(const uint32_t*)(base);
            xa[s][j][1] = *(const uint32_t*)(base + 8 * D);
            xa[s][j][2] = *(const uint32_t*)(base + 8);
            xa[s][j][3] = *(const uint32_t*)(base + 8 * D + 8);
        }
    }

    CPW0();
    __syncthreads();

    const uint32_t* Wh32 = (const uint32_t*)(sm);
    const uint32_t* Wl32 = (const uint32_t*)(sm + QST);

    float s[16][4];
#pragma unroll
    for (int t = 0; t < 16; t++) { s[t][0] = s[t][1] = s[t][2] = s[t][3] = 0.f; }
#pragma unroll
    for (int j = 0; j < 8; j++) {
#pragma unroll
        for (int t = 0; t < 16; t++) {
            int bi = (8 * t + lq) * (WROW / 2) + j * 8 + lr;
            mma(s[t], xa[0][j], Wh32[bi], Wh32[bi + 4]);
        }
#pragma unroll
        for (int t = 0; t < 16; t++) {
            int bi = (8 * t + lq) * (WROW / 2) + j * 8 + lr;
            mma(s[t], xa[1][j], Wh32[bi], Wh32[bi + 4]);
        }
#pragma unroll
        for (int t = 0; t < 16; t++) {
            int bi = (8 * t + lq) * (WROW / 2) + j * 8 + lr;
            mma(s[t], xa[0][j], Wl32[bi], Wl32[bi + 4]);
        }
    }

    if (which < 2) {
        // q: split hi/lo; k: hi only (Kl term dropped in attention)
        __half* oh = (which == 0 ? g_qh : g_kh) + ((size_t)h * NT + n0 + w * 16) * D;
#pragma unroll
        for (int t = 0; t < 16; t++) {
            int col = 8 * t + lr * 2;
            uint32_t h01, l01, h23, l23;
            pack2(s[t][0], s[t][1], h01, l01);
            pack2(s[t][2], s[t][3], h23, l23);
            *(uint32_t*)(oh + (size_t)lq * D + col)       = h01;
            *(uint32_t*)(oh + (size_t)(lq + 8) * D + col) = h23;
            if (which == 0) {
                __half* ol = g_ql + ((size_t)h * NT + n0 + w * 16) * D;
                *(uint32_t*)(ol + (size_t)lq * D + col)       = l01;
                *(uint32_t*)(ol + (size_t)(lq + 8) * D + col) = l23;
            }
        }
    } else {
        __syncthreads();
        float* buf = (float*)sm;
#pragma unroll
        for (int t = 0; t < 16; t++) {
            int c = 8 * t + lr * 2;
            int r0 = w * 16 + lq, r1 = r0 + 8;
            buf[r0 * TP + c] = s[t][0]; buf[r0 * TP + c + 1] = s[t][1];
            buf[r1 * TP + c] = s[t][2]; buf[r1 * TP + c + 1] = s[t][3];
        }
        __syncthreads();
#pragma unroll
        for (int dd = 0; dd < 16; dd++) {
            int d = w * 16 + dd;
            int n4 = l * 4;
            __align__(8) __half hb[4];
#pragma unroll
            for (int i = 0; i < 4; i++)
                hb[i] = __float2half_rn(buf[(n4 + i) * TP + d]);
            *(uint2*)(g_vh + ((size_t)h * D + d) * NT + n0 + n4) = *(uint2*)hb;
        }
    }
}

// ---------------- Wg transpose + final MLP --------------------------------------
__global__ void wgT_kernel(const float* __restrict__ Wg) {
    for (int it = threadIdx.x; it < D * D; it += blockDim.x) {
        int d = it >> 7, f = it & 127;
        g_wgT[f * D + d] = Wg[d * D + f];
    }
}

__global__ void __launch_bounds__(256) final_kernel(const float* __restrict__ x,
                                                    const float* __restrict__ bg,
                                                    float* __restrict__ y) {
    __shared__ float hs[64][D];
    __shared__ float Ws[16][D];
    __shared__ float bsh[D];
    const int n0 = blockIdx.x * 64;
    const int tid = threadIdx.x;

    for (int it = tid; it < 64 * 32; it += 256) {
        int r = it >> 5, c4 = it & 31;
        size_t off = (size_t)(n0 + r) * D + c4 * 4;
        float4 a = *(const float4*)(x + off);
#pragma unroll
        for (int hh = 0; hh < H; hh++) {
            float4 b = *(const float4*)(g_o + (size_t)hh * NT * D + off);
            a.x += b.x; a.y += b.y; a.z += b.z; a.w += b.w;
        }
        *(float4*)&hs[r][c4 * 4] = a;
    }
    if (tid < D) bsh[tid] = bg[tid];

    const int ty = tid >> 4, tx = tid & 15;
    float acc[4][8];
#pragma unroll
    for (int i = 0; i < 4; i++)
#pragma unroll
        for (int j = 0; j < 8; j++) acc[i][j] = 0.f;

    for (int fc = 0; fc < 8; fc++) {
        __syncthreads();
        for (int it = tid; it < 16 * 32; it += 256) {
            int r = it >> 5, c4 = it & 31;
            *(float4*)&Ws[r][c4 * 4] = *(const float4*)(g_wgT + (size_t)(fc * 16 + r) * D + c4 * 4);
        }
        __syncthreads();
#pragma unroll
        for (int f = 0; f < 16; f++) {
            float a[4];
#pragma unroll
            for (int ii = 0; ii < 4; ii++) a[ii] = hs[ty * 4 + ii][fc * 16 + f];
            float4 b0 = *(float4*)&Ws[f][tx * 8];
            float4 b1 = *(float4*)&Ws[f][tx * 8 + 4];
            float b[8] = {b0.x, b0.y, b0.z, b0.w, b1.x, b1.y, b1.z, b1.w};
#pragma unroll
            for (int ii = 0; ii < 4; ii++)
#pragma unroll
                for (int jj = 0; jj < 8; jj++)
                    acc[ii][jj] = fmaf(a[ii], b[jj], acc[ii][jj]);
        }
    }

#pragma unroll
    for (int ii = 0; ii < 4; ii++) {
        int n = n0 + ty * 4 + ii;
#pragma unroll
        for (int jj = 0; jj < 8; jj += 4) {
            int d = tx * 8 + jj;
            float4 xv = *(const float4*)(x + (size_t)n * D + d);
            float4 r;
            r.x = xv.x + fmaxf(acc[ii][jj + 0] + bsh[d + 0], 0.f);
            r.y = xv.y + fmaxf(acc[ii][jj + 1] + bsh[d + 1], 0.f);
            r.z = xv.z + fmaxf(acc[ii][jj + 2] + bsh[d + 2], 0.f);
            r.w = xv.w + fmaxf(acc[ii][jj + 3] + bsh[d + 3], 0.f);
            *(float4*)(y + (size_t)n * D + d) = r;
        }
    }
}

// ---------------- launch ---------------------------------------------------------
extern "C" void kernel_launch(void* const* d_in, const int* in_sizes, int n_in,
                              void* d_out, int out_size) {
    const float* x  = (const float*)d_in[0];
    const float* Wk = (const float*)d_in[1];
    const float* Wq = (const float*)d_in[2];
    const float* Wv = (const float*)d_in[3];
    const float* Wm = (const float*)d_in[4];
    const float* Wg = (const float*)d_in[5];
    const float* bg = (const float*)d_in[6];
    float* y = (float*)d_out;

    cudaFuncSetAttribute(attn_kernel, cudaFuncAttributeMaxDynamicSharedMemorySize, ASMEM);
    cudaFuncSetAttribute(qkv_mma_kernel, cudaFuncAttributeMaxDynamicSharedMemorySize, QSMEM);

    reset_ctr_kernel<<<1, 1>>>();
    splitx_kernel<<<NT * D / (256 * 8), 256>>>(x);
    splitW_kernel<<<dim3(H, 3), 256>>>(Wk, Wq, Wv);
    qkv_mma_kernel<<<dim3(NT / 128, H, 3), 256, QSMEM>>>();
    attn_kernel<<<PGRID, 128, ASMEM>>>(Wm);
    wgT_kernel<<<1, 256>>>(Wg);
    final_kernel<<<NT / 64, 256>>>(x, bg, y);
}

// round 14
// speedup vs baseline: 1.4638x; 1.0729x over previous
#include <cuda_runtime.h>
#include <cuda_fp16.h>
#include <cstdint>

#define NT 4096
#define D  128
#define H  8
#define BN 64
#define NB (NT / BN)
#define NTILES 512          // 64 q-tiles x 8 heads
#define PGRID 304           // 2 CTAs/SM x 152 SMs

// ---------------- scratch globals ---------------------------------------------
__device__ __align__(16) __half g_qh[H * NT * D];
__device__ __align__(16) __half g_ql[H * NT * D];
__device__ __align__(16) __half g_kh[H * NT * D];
__device__ __align__(16) __half g_vh[H * D * NT];   // transposed [h][d][n]
__device__ __align__(16) float  g_o[H * NT * D];
__device__ float g_wgT[D * D];
__device__ unsigned int g_ctr;

__device__ __align__(16) __half g_xh[NT * D];
__device__ __align__(16) __half g_xl[NT * D];
__device__ __align__(16) __half g_wT[3][2][H * D * D];   // [which][hi/lo][h][dout][f]

// ---------------- helpers -------------------------------------------------------
__device__ __forceinline__ float ex2f(float x) {
    float y; asm("ex2.approx.ftz.f32 %0,%1;" : "=f"(y) : "f"(x)); return y;
}
#define CP16(d, s) asm volatile("cp.async.cg.shared.global [%0],[%1],16;" :: "r"(d), "l"(s) : "memory")
#define CPC()  asm volatile("cp.async.commit_group;" ::: "memory")
#define CPW0() asm volatile("cp.async.wait_group 0;" ::: "memory")
#define CPW1() asm volatile("cp.async.wait_group 1;" ::: "memory")

__device__ __forceinline__ uint32_t su32(const void* p) {
    return (uint32_t)__cvta_generic_to_shared(p);
}

__device__ __forceinline__ void mma(float* c, const uint32_t* a, uint32_t b0, uint32_t b1) {
    asm volatile(
        "mma.sync.aligned.m16n8k16.row.col.f32.f16.f16.f32 "
        "{%0,%1,%2,%3},{%4,%5,%6,%7},{%8,%9},{%0,%1,%2,%3};"
        : "+f"(c[0]), "+f"(c[1]), "+f"(c[2]), "+f"(c[3])
        : "r"(a[0]), "r"(a[1]), "r"(a[2]), "r"(a[3]), "r"(b0), "r"(b1));
}

__device__ __forceinline__ void pack2(float a, float b, uint32_t& hi, uint32_t& lo) {
    __half2 h = __floats2half2_rn(a, b);
    float2 f = __half22float2(h);
    __half2 r = __floats2half2_rn(a - f.x, b - f.y);
    hi = *(uint32_t*)&h; lo = *(uint32_t*)&r;
}

// pack to fp16 pair AND accumulate the rounded-value sum (for consistent l)
__device__ __forceinline__ uint32_t packsum(float a, float b, float& acc) {
    __half2 h = __floats2half2_rn(a, b);
    float2 f = __half22float2(h);
    acc += f.x + f.y;
    return *(uint32_t*)&h;
}

// ================== attention smem: 3 stages of (Kh[64][136] | V[128][72]) ======
#define KST    17408
#define VST    18432
#define STG    (KST + VST)              // 35840
#define ASMEM  (3 * STG)                // 107520

__device__ __forceinline__ void load_stage(uint32_t sb, int h, int kb, int tid, int slot) {
    size_t kof = (size_t)h * NT * D + (size_t)kb * BN * D;
    size_t vof = (size_t)h * D * NT + (size_t)kb * BN;
    uint32_t kbase = sb + (uint32_t)slot * STG;
    uint32_t vbase = kbase + KST;
    for (int c = tid; c < 1024; c += 128) {          // Kh: 64 rows x 16 chunks
        int r = c >> 4, k = c & 15;
        CP16(kbase + (uint32_t)(r * 272 + k * 16), g_kh + kof + (size_t)r * D + k * 8);
    }
    for (int c = tid; c < 1024; c += 128) {          // V: 128 dim-rows x 8 chunks
        int r = c >> 3, k = c & 7;
        CP16(vbase + (uint32_t)(r * 144 + k * 16), g_vh + vof + (size_t)r * NT + k * 8);
    }
}

__global__ void reset_ctr_kernel() { g_ctr = 0u; }

// ---------------- attention: persistent, grid 304, 128 threads, 2 CTAs/SM -------
__global__ void __launch_bounds__(128, 2) attn_kernel(const float* __restrict__ W_m) {
    extern __shared__ char sm[];
    __shared__ unsigned int sidx;
    const int tid = threadIdx.x, w = tid >> 5, l = tid & 31;
    const int lq = l >> 2, lr = l & 3;
    const uint32_t sb = su32(sm);
    const float L2E = 1.4426950408889634f;

    while (true) {
        if (tid == 0) sidx = atomicAdd(&g_ctr, 1u);
        __syncthreads();
        const unsigned int idx = sidx;
        if (idx >= NTILES) break;
        const int h = (int)(idx >> 6);
        const int q0 = (int)(idx & 63) * 64;

        // prologue: stages 0,1 in flight; g0 guaranteed done before first barrier
        load_stage(sb, h, 0, tid, 0); CPC();
        load_stage(sb, h, 1, tid, 1); CPC();

        // Q fragments hi/lo (regs) — overlaps with async loads
        uint32_t qa[2][8][4];
#pragma unroll
        for (int s = 0; s < 2; s++) {
            const __half* qs = (s ? g_ql : g_qh) + ((size_t)h * NT + q0 + w * 16) * D;
#pragma unroll
            for (int j = 0; j < 8; j++) {
                const __half* base = qs + (size_t)lq * D + j * 16 + lr * 2;
                qa[s][j][0] = *(const uint32_t*)(base);
                qa[s][j][1] = *(const uint32_t*)(base + 8 * D);
                qa[s][j][2] = *(const uint32_t*)(base + 8);
                qa[s][j][3] = *(const uint32_t*)(base + 8 * D + 8);
            }
        }
        CPW1();   // group 0 complete

        float o[16][4];
#pragma unroll
        for (int t = 0; t < 16; t++) { o[t][0] = o[t][1] = o[t][2] = o[t][3] = 0.f; }
        float m0 = -1e30f, m1 = -1e30f, l0 = 0.f, l1 = 0.f;

        for (int kb = 0; kb < NB; kb++) {
            __syncthreads();                     // stage kb visible; slot (kb+2)%3 free
            if (kb + 2 < NB) load_stage(sb, h, kb + 2, tid, (kb + 2) % 3);
            CPC();
            CPW1();                              // group kb+1 complete (for next iter)

            const char* stg = sm + (kb % 3) * STG;
            const uint32_t* Kh32 = (const uint32_t*)(stg);
            const uint32_t* Vh32 = (const uint32_t*)(stg + KST);

            // ---- S = QhKh + QlKh — accumulator-interleaved sweeps ----
            float s[8][4];
#pragma unroll
            for (int t = 0; t < 8; t++) { s[t][0] = s[t][1] = s[t][2] = s[t][3] = 0.f; }
#pragma unroll
            for (int j = 0; j < 8; j++) {
                uint32_t bh[8][2];
#pragma unroll
                for (int t = 0; t < 8; t++) {
                    int bi = (8 * t + lq) * 68 + j * 8 + lr;
                    bh[t][0] = Kh32[bi]; bh[t][1] = Kh32[bi + 4];
                }
#pragma unroll
                for (int t = 0; t < 8; t++) mma(s[t], qa[0][j], bh[t][0], bh[t][1]);
#pragma unroll
                for (int t = 0; t < 8; t++) mma(s[t], qa[1][j], bh[t][0], bh[t][1]);
            }

            // ---- online softmax ----
            float rx0 = -1e30f, rx1 = -1e30f;
#pragma unroll
            for (int t = 0; t < 8; t++) {
                rx0 = fmaxf(rx0, fmaxf(s[t][0], s[t][1]));
                rx1 = fmaxf(rx1, fmaxf(s[t][2], s[t][3]));
            }
            rx0 = fmaxf(rx0, __shfl_xor_sync(~0u, rx0, 1));
            rx0 = fmaxf(rx0, __shfl_xor_sync(~0u, rx0, 2));
            rx1 = fmaxf(rx1, __shfl_xor_sync(~0u, rx1, 1));
            rx1 = fmaxf(rx1, __shfl_xor_sync(~0u, rx1, 2));
            float mn0 = fmaxf(m0, rx0), mn1 = fmaxf(m1, rx1);
            float sc0 = ex2f((m0 - mn0) * L2E), sc1 = ex2f((m1 - mn1) * L2E);
            m0 = mn0; m1 = mn1;
#pragma unroll
            for (int t = 0; t < 8; t++) {
                s[t][0] = ex2f((s[t][0] - mn0) * L2E);
                s[t][1] = ex2f((s[t][1] - mn0) * L2E);
                s[t][2] = ex2f((s[t][2] - mn1) * L2E);
                s[t][3] = ex2f((s[t][3] - mn1) * L2E);
            }

            // ---- pack P (fp16) and sum the ROUNDED values for l ----
            float rs0 = 0.f, rs1 = 0.f;
            uint32_t ph[4][4];
#pragma unroll
            for (int j = 0; j < 4; j++) {
                ph[j][0] = packsum(s[2 * j][0],     s[2 * j][1],     rs0);
                ph[j][1] = packsum(s[2 * j][2],     s[2 * j][3],     rs1);
                ph[j][2] = packsum(s[2 * j + 1][0], s[2 * j + 1][1], rs0);
                ph[j][3] = packsum(s[2 * j + 1][2], s[2 * j + 1][3], rs1);
            }
            rs0 += __shfl_xor_sync(~0u, rs0, 1); rs0 += __shfl_xor_sync(~0u, rs0, 2);
            rs1 += __shfl_xor_sync(~0u, rs1, 1); rs1 += __shfl_xor_sync(~0u, rs1, 2);
            l0 = l0 * sc0 + rs0; l1 = l1 * sc1 + rs1;
#pragma unroll
            for (int t = 0; t < 16; t++) {
                o[t][0] *= sc0; o[t][1] *= sc0; o[t][2] *= sc1; o[t][3] *= sc1;
            }

            // ---- O += PhVh — accumulator-interleaved sweep ----
#pragma unroll
            for (int j = 0; j < 4; j++) {
                uint32_t vb[16][2];
#pragma unroll
                for (int t = 0; t < 16; t++) {
                    int bi = (8 * t + lq) * 36 + j * 8 + lr;
                    vb[t][0] = Vh32[bi]; vb[t][1] = Vh32[bi + 4];
                }
#pragma unroll
                for (int t = 0; t < 16; t++) mma(o[t], ph[j], vb[t][0], vb[t][1]);
            }
        }

        float wm = W_m[h];
        float i0 = wm / l0, i1 = wm / l1;
        float* og = g_o + ((size_t)h * NT + q0 + w * 16) * D;
#pragma unroll
        for (int t = 0; t < 16; t++) {
            int col = 8 * t + lr * 2;
            *(float2*)(og + (size_t)lq * D + col)       = make_float2(o[t][0] * i0, o[t][1] * i0);
            *(float2*)(og + (size_t)(lq + 8) * D + col) = make_float2(o[t][2] * i1, o[t][3] * i1);
        }
        __syncthreads();   // smem reads done before next tile's prologue loads
    }
}

// ================== prep: split x, split+transpose W ============================
__global__ void __launch_bounds__(256) splitx_kernel(const float* __restrict__ x) {
    int base = (blockIdx.x * 256 + threadIdx.x) * 8;
    float4 a = *(const float4*)(x + base);
    float4 b = *(const float4*)(x + base + 4);
    float v[8] = {a.x, a.y, a.z, a.w, b.x, b.y, b.z, b.w};
    __align__(16) __half hb[8], lb[8];
#pragma unroll
    for (int i = 0; i < 8; i++) {
        __half hh = __float2half_rn(v[i]);
        hb[i] = hh;
        lb[i] = __float2half_rn(v[i] - __half2float(hh));
    }
    *(uint4*)(g_xh + base) = *(uint4*)hb;
    *(uint4*)(g_xl + base) = *(uint4*)lb;
}

__global__ void __launch_bounds__(256) splitW_kernel(const float* __restrict__ Wk,
                                                     const float* __restrict__ Wq,
                                                     const float* __restrict__ Wv) {
    const int h = blockIdx.x, which = blockIdx.y;
    const float* W = (which == 0 ? Wq : which == 1 ? Wk : Wv) + (size_t)h * D * D;
    __half* oh = g_wT[which][0] + (size_t)h * D * D;
    __half* ol = g_wT[which][1] + (size_t)h * D * D;
    for (int idx = threadIdx.x; idx < D * D; idx += 256) {
        int dout = idx >> 7, f = idx & 127;
        float v = W[(size_t)f * D + dout];
        __half hh = __float2half_rn(v);
        oh[idx] = hh;
        ol[idx] = __float2half_rn(v - __half2float(hh));
    }
}

// ================== qkv via HMMA: grid (64, 8, 3), 128 threads, 3 CTAs/SM ======
#define WROW 136
#define QST  (128 * WROW * 2)
#define QSMEM (2 * QST)
#define TP 133

__global__ void __launch_bounds__(128, 3) qkv_mma_kernel() {
    extern __shared__ char sm[];
    const int tid = threadIdx.x, w = tid >> 5, l = tid & 31;
    const int tile = blockIdx.x, h = blockIdx.y, which = blockIdx.z;
    const int lq = l >> 2, lr = l & 3;
    const int n0 = tile * 64;

    {
        const uint32_t sb = su32(sm);
        const __half* wh = g_wT[which][0] + (size_t)h * D * D;
        const __half* wl = g_wT[which][1] + (size_t)h * D * D;
        for (int c = tid; c < 2048; c += 128) {
            int r = c >> 4, k = c & 15;
            uint32_t so = (uint32_t)(r * (WROW * 2) + k * 16);
            CP16(sb + so,       wh + (size_t)r * D + k * 8);
            CP16(sb + QST + so, wl + (size_t)r * D + k * 8);
        }
        CPC();
    }

    uint32_t xa[2][8][4];
#pragma unroll
    for (int s = 0; s < 2; s++) {
        const __half* xs = (s ? g_xl : g_xh) + (size_t)(n0 + w * 16) * D;
#pragma unroll
        for (int j = 0; j < 8; j++) {
            const __half* base = xs + (size_t)lq * D + j * 16 + lr * 2;
            xa[s][j][0] = *(const uint32_t*)(base);
            xa[s][j][1] = *(const uint32_t*)(base + 8 * D);
            xa[s][j][2] = *(const uint32_t*)(base + 8);
            xa[s][j][3] = *(const uint32_t*)(base + 8 * D + 8);
        }
    }

    CPW0();
    __syncthreads();

    const uint32_t* Wh32 = (const uint32_t*)(sm);
    const uint32_t* Wl32 = (const uint32_t*)(sm + QST);

    float s[16][4];
#pragma unroll
    for (int t = 0; t < 16; t++) { s[t][0] = s[t][1] = s[t][2] = s[t][3] = 0.f; }
#pragma unroll
    for (int j = 0; j < 8; j++) {
#pragma unroll
        for (int t = 0; t < 16; t++) {
            int bi = (8 * t + lq) * (WROW / 2) + j * 8 + lr;
            mma(s[t], xa[0][j], Wh32[bi], Wh32[bi + 4]);
        }
#pragma unroll
        for (int t = 0; t < 16; t++) {
            int bi = (8 * t + lq) * (WROW / 2) + j * 8 + lr;
            mma(s[t], xa[1][j], Wh32[bi], Wh32[bi + 4]);
        }
#pragma unroll
        for (int t = 0; t < 16; t++) {
            int bi = (8 * t + lq) * (WROW / 2) + j * 8 + lr;
            mma(s[t], xa[0][j], Wl32[bi], Wl32[bi + 4]);
        }
    }

    if (which < 2) {
        // q: split hi/lo; k: hi only (Kl term dropped in attention)
        __half* oh = (which == 0 ? g_qh : g_kh) + ((size_t)h * NT + n0 + w * 16) * D;
#pragma unroll
        for (int t = 0; t < 16; t++) {
            int col = 8 * t + lr * 2;
            uint32_t h01, l01, h23, l23;
            pack2(s[t][0], s[t][1], h01, l01);
            pack2(s[t][2], s[t][3], h23, l23);
            *(uint32_t*)(oh + (size_t)lq * D + col)       = h01;
            *(uint32_t*)(oh + (size_t)(lq + 8) * D + col) = h23;
            if (which == 0) {
                __half* ol = g_ql + ((size_t)h * NT + n0 + w * 16) * D;
                *(uint32_t*)(ol + (size_t)lq * D + col)       = l01;
                *(uint32_t*)(ol + (size_t)(lq + 8) * D + col) = l23;
            }
        }
    } else {
        // v: transpose 64 rows via smem, store [h][d][n] fp16 coalesced
        __syncthreads();
        float* buf = (float*)sm;   // [64][TP]
#pragma unroll
        for (int t = 0; t < 16; t++) {
            int c = 8 * t + lr * 2;
            int r0 = w * 16 + lq, r1 = r0 + 8;
            buf[r0 * TP + c] = s[t][0]; buf[r0 * TP + c + 1] = s[t][1];
            buf[r1 * TP + c] = s[t][2]; buf[r1 * TP + c + 1] = s[t][3];
        }
        __syncthreads();
#pragma unroll
        for (int dd = 0; dd < 32; dd++) {
            int d = w * 32 + dd;
            int n2 = l * 2;
            __half hb[2];
            hb[0] = __float2half_rn(buf[n2 * TP + d]);
            hb[1] = __float2half_rn(buf[(n2 + 1) * TP + d]);
            *(uint32_t*)(g_vh + ((size_t)h * D + d) * NT + n0 + n2) = *(uint32_t*)hb;
        }
    }
}

// ---------------- Wg transpose + final MLP --------------------------------------
__global__ void wgT_kernel(const float* __restrict__ Wg) {
    int it = blockIdx.x * 256 + threadIdx.x;
    if (it < D * D) {
        int d = it >> 7, f = it & 127;
        g_wgT[f * D + d] = Wg[d * D + f];
    }
}

// grid 256 (16 rows per CTA), 256 threads
__global__ void __launch_bounds__(256) final_kernel(const float* __restrict__ x,
                                                    const float* __restrict__ bg,
                                                    float* __restrict__ y) {
    __shared__ float hs[16][132];
    __shared__ float Ws[16][132];
    __shared__ float bsh[D];
    const int n0 = blockIdx.x * 16;
    const int tid = threadIdx.x;

    for (int it = tid; it < 16 * 32; it += 256) {
        int r = it >> 5, c4 = it & 31;
        size_t off = (size_t)(n0 + r) * D + c4 * 4;
        float4 a = *(const float4*)(x + off);
#pragma unroll
        for (int hh = 0; hh < H; hh++) {
            float4 b = *(const float4*)(g_o + (size_t)hh * NT * D + off);
            a.x += b.x; a.y += b.y; a.z += b.z; a.w += b.w;
        }
        *(float4*)&hs[r][c4 * 4] = a;
    }
    if (tid < D) bsh[tid] = bg[tid];

    const int ty = tid >> 4, tx = tid & 15;   // row ty (16), col-group tx (16x8)
    float acc[8];
#pragma unroll
    for (int j = 0; j < 8; j++) acc[j] = 0.f;

    for (int fc = 0; fc < 8; fc++) {
        __syncthreads();
        for (int it = tid; it < 16 * 32; it += 256) {
            int r = it >> 5, c4 = it & 31;
            *(float4*)&Ws[r][c4 * 4] = *(const float4*)(g_wgT + (size_t)(fc * 16 + r) * D + c4 * 4);
        }
        __syncthreads();
#pragma unroll
        for (int f = 0; f < 16; f++) {
            float a = hs[ty][fc * 16 + f];
            float4 b0 = *(float4*)&Ws[f][tx * 8];
            float4 b1 = *(float4*)&Ws[f][tx * 8 + 4];
            acc[0] = fmaf(a, b0.x, acc[0]); acc[1] = fmaf(a, b0.y, acc[1]);
            acc[2] = fmaf(a, b0.z, acc[2]); acc[3] = fmaf(a, b0.w, acc[3]);
            acc[4] = fmaf(a, b1.x, acc[4]); acc[5] = fmaf(a, b1.y, acc[5]);
            acc[6] = fmaf(a, b1.z, acc[6]); acc[7] = fmaf(a, b1.w, acc[7]);
        }
    }

    {
        int n = n0 + ty;
#pragma unroll
        for (int jj = 0; jj < 8; jj += 4) {
            int d = tx * 8 + jj;
            float4 xv = *(const float4*)(x + (size_t)n * D + d);
            float4 r;
            r.x = xv.x + fmaxf(acc[jj + 0] + bsh[d + 0], 0.f);
            r.y = xv.y + fmaxf(acc[jj + 1] + bsh[d + 1], 0.f);
            r.z = xv.z + fmaxf(acc[jj + 2] + bsh[d + 2], 0.f);
            r.w = xv.w + fmaxf(acc[jj + 3] + bsh[d + 3], 0.f);
            *(float4*)(y + (size_t)n * D + d) = r;
        }
    }
}

// ---------------- launch ---------------------------------------------------------
extern "C" void kernel_launch(void* const* d_in, const int* in_sizes, int n_in,
                              void* d_out, int out_size) {
    const float* x  = (const float*)d_in[0];
    const float* Wk = (const float*)d_in[1];
    const float* Wq = (const float*)d_in[2];
    const float* Wv = (const float*)d_in[3];
    const float* Wm = (const float*)d_in[4];
    const float* Wg = (const float*)d_in[5];
    const float* bg = (const float*)d_in[6];
    float* y = (float*)d_out;

    cudaFuncSetAttribute(attn_kernel, cudaFuncAttributeMaxDynamicSharedMemorySize, ASMEM);
    cudaFuncSetAttribute(qkv_mma_kernel, cudaFuncAttributeMaxDynamicSharedMemorySize, QSMEM);

    reset_ctr_kernel<<<1, 1>>>();
    splitx_kernel<<<NT * D / (256 * 8), 256>>>(x);
    splitW_kernel<<<dim3(H, 3), 256>>>(Wk, Wq, Wv);
    wgT_kernel<<<(D * D + 255) / 256, 256>>>(Wg);
    qkv_mma_kernel<<<dim3(NT / 64, H, 3), 128, QSMEM>>>();
    attn_kernel<<<PGRID, 128, ASMEM>>>(Wm);
    final_kernel<<<NT / 16, 256>>>(x, bg, y);
}

// round 15
// speedup vs baseline: 1.8052x; 1.2332x over previous
#include <cuda_runtime.h>
#include <cuda_fp16.h>
#include <cstdint>

#define NT 4096
#define D  128
#define H  8
#define BN 64
#define NB (NT / BN)
#define NTILES 512          // 64 q-tiles x 8 heads
#define PGRID 456           // 3 CTAs/SM x 152 SMs

// ---------------- scratch globals ---------------------------------------------
__device__ __align__(16) __half g_qh[H * NT * D];
__device__ __align__(16) __half g_kh[H * NT * D];
__device__ __align__(16) __half g_vh[H * D * NT];   // transposed [h][d][n]
__device__ __align__(16) float  g_o[H * NT * D];
__device__ float g_wgT[D * D];
__device__ unsigned int g_ctr;

__device__ __align__(16) __half g_xh[NT * D];
__device__ __align__(16) __half g_xl[NT * D];
__device__ __align__(16) __half g_wT[3][2][H * D * D];   // [which][hi/lo][h][dout][f]

// ---------------- helpers -------------------------------------------------------
__device__ __forceinline__ float ex2f(float x) {
    float y; asm("ex2.approx.ftz.f32 %0,%1;" : "=f"(y) : "f"(x)); return y;
}
#define CP16(d, s) asm volatile("cp.async.cg.shared.global [%0],[%1],16;" :: "r"(d), "l"(s) : "memory")
#define CPC()  asm volatile("cp.async.commit_group;" ::: "memory")
#define CPW0() asm volatile("cp.async.wait_group 0;" ::: "memory")
#define CPW1() asm volatile("cp.async.wait_group 1;" ::: "memory")

__device__ __forceinline__ uint32_t su32(const void* p) {
    return (uint32_t)__cvta_generic_to_shared(p);
}

__device__ __forceinline__ void mma(float* c, const uint32_t* a, uint32_t b0, uint32_t b1) {
    asm volatile(
        "mma.sync.aligned.m16n8k16.row.col.f32.f16.f16.f32 "
        "{%0,%1,%2,%3},{%4,%5,%6,%7},{%8,%9},{%0,%1,%2,%3};"
        : "+f"(c[0]), "+f"(c[1]), "+f"(c[2]), "+f"(c[3])
        : "r"(a[0]), "r"(a[1]), "r"(a[2]), "r"(a[3]), "r"(b0), "r"(b1));
}

__device__ __forceinline__ void pack2(float a, float b, uint32_t& hi, uint32_t& lo) {
    __half2 h = __floats2half2_rn(a, b);
    float2 f = __half22float2(h);
    __half2 r = __floats2half2_rn(a - f.x, b - f.y);
    hi = *(uint32_t*)&h; lo = *(uint32_t*)&r;
}

__device__ __forceinline__ uint32_t packhi(float a, float b) {
    __half2 h = __floats2half2_rn(a, b);
    return *(uint32_t*)&h;
}

// pack to fp16 pair AND accumulate the rounded-value sum (for consistent l)
__device__ __forceinline__ uint32_t packsum(float a, float b, float& acc) {
    __half2 h = __floats2half2_rn(a, b);
    float2 f = __half22float2(h);
    acc += f.x + f.y;
    return *(uint32_t*)&h;
}

// ================== attention smem: 2 stages of (Kh[64][136] | V[128][72]) ======
#define KST    17408
#define VST    18432
#define STG    (KST + VST)              // 35840
#define ASMEM  (2 * STG)                // 71680  -> 3 CTAs/SM = 215KB

__device__ __forceinline__ void load_stage(uint32_t sb, int h, int kb, int tid, int slot) {
    size_t kof = (size_t)h * NT * D + (size_t)kb * BN * D;
    size_t vof = (size_t)h * D * NT + (size_t)kb * BN;
    uint32_t kbase = sb + (uint32_t)slot * STG;
    uint32_t vbase = kbase + KST;
    for (int c = tid; c < 1024; c += 128) {          // Kh: 64 rows x 16 chunks
        int r = c >> 4, k = c & 15;
        CP16(kbase + (uint32_t)(r * 272 + k * 16), g_kh + kof + (size_t)r * D + k * 8);
    }
    for (int c = tid; c < 1024; c += 128) {          // V: 128 dim-rows x 8 chunks
        int r = c >> 3, k = c & 7;
        CP16(vbase + (uint32_t)(r * 144 + k * 16), g_vh + vof + (size_t)r * NT + k * 8);
    }
}

__global__ void reset_ctr_kernel() { g_ctr = 0u; }

// ---------------- attention: persistent, grid 456, 128 threads, 3 CTAs/SM -------
__global__ void __launch_bounds__(128, 3) attn_kernel(const float* __restrict__ W_m) {
    extern __shared__ char sm[];
    __shared__ unsigned int sidx;
    const int tid = threadIdx.x, w = tid >> 5, l = tid & 31;
    const int lq = l >> 2, lr = l & 3;
    const uint32_t sb = su32(sm);
    const float L2E = 1.4426950408889634f;

    while (true) {
        if (tid == 0) sidx = atomicAdd(&g_ctr, 1u);
        __syncthreads();
        const unsigned int idx = sidx;
        if (idx >= NTILES) break;
        const int h = (int)(idx >> 6);
        const int q0 = (int)(idx & 63) * 64;

        load_stage(sb, h, 0, tid, 0); CPC();

        // Q fragments (fp16 hi only) — overlaps with async loads
        uint32_t qa[8][4];
        {
            const __half* qs = g_qh + ((size_t)h * NT + q0 + w * 16) * D;
#pragma unroll
            for (int j = 0; j < 8; j++) {
                const __half* base = qs + (size_t)lq * D + j * 16 + lr * 2;
                qa[j][0] = *(const uint32_t*)(base);
                qa[j][1] = *(const uint32_t*)(base + 8 * D);
                qa[j][2] = *(const uint32_t*)(base + 8);
                qa[j][3] = *(const uint32_t*)(base + 8 * D + 8);
            }
        }

        float o[16][4];
#pragma unroll
        for (int t = 0; t < 16; t++) { o[t][0] = o[t][1] = o[t][2] = o[t][3] = 0.f; }
        float m0 = -1e30f, m1 = -1e30f, l0 = 0.f, l1 = 0.f;

        for (int kb = 0; kb < NB; kb++) {
            __syncthreads();                 // all warps done reading slot (kb+1)&1
            if (kb + 1 < NB) load_stage(sb, h, kb + 1, tid, (kb + 1) & 1);
            CPC(); CPW1();                   // stage kb complete
            __syncthreads();

            const char* stg = sm + (kb & 1) * STG;
            const uint32_t* Kh32 = (const uint32_t*)(stg);
            const uint32_t* Vh32 = (const uint32_t*)(stg + KST);

            // ---- S = QhKh — single-term, accumulator-interleaved ----
            float s[8][4];
#pragma unroll
            for (int t = 0; t < 8; t++) { s[t][0] = s[t][1] = s[t][2] = s[t][3] = 0.f; }
#pragma unroll
            for (int j = 0; j < 8; j++) {
                uint32_t bh[8][2];
#pragma unroll
                for (int t = 0; t < 8; t++) {
                    int bi = (8 * t + lq) * 68 + j * 8 + lr;
                    bh[t][0] = Kh32[bi]; bh[t][1] = Kh32[bi + 4];
                }
#pragma unroll
                for (int t = 0; t < 8; t++) mma(s[t], qa[j], bh[t][0], bh[t][1]);
            }

            // ---- online softmax ----
            float rx0 = -1e30f, rx1 = -1e30f;
#pragma unroll
            for (int t = 0; t < 8; t++) {
                rx0 = fmaxf(rx0, fmaxf(s[t][0], s[t][1]));
                rx1 = fmaxf(rx1, fmaxf(s[t][2], s[t][3]));
            }
            rx0 = fmaxf(rx0, __shfl_xor_sync(~0u, rx0, 1));
            rx0 = fmaxf(rx0, __shfl_xor_sync(~0u, rx0, 2));
            rx1 = fmaxf(rx1, __shfl_xor_sync(~0u, rx1, 1));
            rx1 = fmaxf(rx1, __shfl_xor_sync(~0u, rx1, 2));
            float mn0 = fmaxf(m0, rx0), mn1 = fmaxf(m1, rx1);
            float sc0 = ex2f((m0 - mn0) * L2E), sc1 = ex2f((m1 - mn1) * L2E);
            m0 = mn0; m1 = mn1;
#pragma unroll
            for (int t = 0; t < 8; t++) {
                s[t][0] = ex2f((s[t][0] - mn0) * L2E);
                s[t][1] = ex2f((s[t][1] - mn0) * L2E);
                s[t][2] = ex2f((s[t][2] - mn1) * L2E);
                s[t][3] = ex2f((s[t][3] - mn1) * L2E);
            }

            // ---- pack P (fp16) and sum the ROUNDED values for l ----
            float rs0 = 0.f, rs1 = 0.f;
            uint32_t ph[4][4];
#pragma unroll
            for (int j = 0; j < 4; j++) {
                ph[j][0] = packsum(s[2 * j][0],     s[2 * j][1],     rs0);
                ph[j][1] = packsum(s[2 * j][2],     s[2 * j][3],     rs1);
                ph[j][2] = packsum(s[2 * j + 1][0], s[2 * j + 1][1], rs0);
                ph[j][3] = packsum(s[2 * j + 1][2], s[2 * j + 1][3], rs1);
            }
            rs0 += __shfl_xor_sync(~0u, rs0, 1); rs0 += __shfl_xor_sync(~0u, rs0, 2);
            rs1 += __shfl_xor_sync(~0u, rs1, 1); rs1 += __shfl_xor_sync(~0u, rs1, 2);
            l0 = l0 * sc0 + rs0; l1 = l1 * sc1 + rs1;
#pragma unroll
            for (int t = 0; t < 16; t++) {
                o[t][0] *= sc0; o[t][1] *= sc0; o[t][2] *= sc1; o[t][3] *= sc1;
            }

            // ---- O += PhVh — accumulator-interleaved sweep ----
#pragma unroll
            for (int j = 0; j < 4; j++) {
                uint32_t vb[16][2];
#pragma unroll
                for (int t = 0; t < 16; t++) {
                    int bi = (8 * t + lq) * 36 + j * 8 + lr;
                    vb[t][0] = Vh32[bi]; vb[t][1] = Vh32[bi + 4];
                }
#pragma unroll
                for (int t = 0; t < 16; t++) mma(o[t], ph[j], vb[t][0], vb[t][1]);
            }
        }

        float wm = W_m[h];
        float i0 = wm / l0, i1 = wm / l1;
        float* og = g_o + ((size_t)h * NT + q0 + w * 16) * D;
#pragma unroll
        for (int t = 0; t < 16; t++) {
            int col = 8 * t + lr * 2;
            *(float2*)(og + (size_t)lq * D + col)       = make_float2(o[t][0] * i0, o[t][1] * i0);
            *(float2*)(og + (size_t)(lq + 8) * D + col) = make_float2(o[t][2] * i1, o[t][3] * i1);
        }
        __syncthreads();   // smem reads done before next tile's prologue loads
    }
}

// ================== prep: split x, split+transpose W ============================
__global__ void __launch_bounds__(256) splitx_kernel(const float* __restrict__ x) {
    int base = (blockIdx.x * 256 + threadIdx.x) * 8;
    float4 a = *(const float4*)(x + base);
    float4 b = *(const float4*)(x + base + 4);
    float v[8] = {a.x, a.y, a.z, a.w, b.x, b.y, b.z, b.w};
    __align__(16) __half hb[8], lb[8];
#pragma unroll
    for (int i = 0; i < 8; i++) {
        __half hh = __float2half_rn(v[i]);
        hb[i] = hh;
        lb[i] = __float2half_rn(v[i] - __half2float(hh));
    }
    *(uint4*)(g_xh + base) = *(uint4*)hb;
    *(uint4*)(g_xl + base) = *(uint4*)lb;
}

__global__ void __launch_bounds__(256) splitW_kernel(const float* __restrict__ Wk,
                                                     const float* __restrict__ Wq,
                                                     const float* __restrict__ Wv) {
    const int h = blockIdx.x, which = blockIdx.y;
    const float* W = (which == 0 ? Wq : which == 1 ? Wk : Wv) + (size_t)h * D * D;
    __half* oh = g_wT[which][0] + (size_t)h * D * D;
    __half* ol = g_wT[which][1] + (size_t)h * D * D;
    for (int idx = threadIdx.x; idx < D * D; idx += 256) {
        int dout = idx >> 7, f = idx & 127;
        float v = W[(size_t)f * D + dout];
        __half hh = __float2half_rn(v);
        oh[idx] = hh;
        ol[idx] = __float2half_rn(v - __half2float(hh));
    }
}

// ================== qkv via HMMA: grid (64, 8, 3), 128 threads, 3 CTAs/SM ======
#define WROW 136
#define QST  (128 * WROW * 2)
#define QSMEM (2 * QST)
#define TP 133

__global__ void __launch_bounds__(128, 3) qkv_mma_kernel() {
    extern __shared__ char sm[];
    const int tid = threadIdx.x, w = tid >> 5, l = tid & 31;
    const int tile = blockIdx.x, h = blockIdx.y, which = blockIdx.z;
    const int lq = l >> 2, lr = l & 3;
    const int n0 = tile * 64;

    {
        const uint32_t sb = su32(sm);
        const __half* wh = g_wT[which][0] + (size_t)h * D * D;
        const __half* wl = g_wT[which][1] + (size_t)h * D * D;
        for (int c = tid; c < 2048; c += 128) {
            int r = c >> 4, k = c & 15;
            uint32_t so = (uint32_t)(r * (WROW * 2) + k * 16);
            CP16(sb + so,       wh + (size_t)r * D + k * 8);
            CP16(sb + QST + so, wl + (size_t)r * D + k * 8);
        }
        CPC();
    }

    uint32_t xa[2][8][4];
#pragma unroll
    for (int s = 0; s < 2; s++) {
        const __half* xs = (s ? g_xl : g_xh) + (size_t)(n0 + w * 16) * D;
#pragma unroll
        for (int j = 0; j < 8; j++) {
            const __half* base = xs + (size_t)lq * D + j * 16 + lr * 2;
            xa[s][j][0] = *(const uint32_t*)(base);
            xa[s][j][1] = *(const uint32_t*)(base + 8 * D);
            xa[s][j][2] = *(const uint32_t*)(base + 8);
            xa[s][j][3] = *(const uint32_t*)(base + 8 * D + 8);
        }
    }

    CPW0();
    __syncthreads();

    const uint32_t* Wh32 = (const uint32_t*)(sm);
    const uint32_t* Wl32 = (const uint32_t*)(sm + QST);

    float s[16][4];
#pragma unroll
    for (int t = 0; t < 16; t++) { s[t][0] = s[t][1] = s[t][2] = s[t][3] = 0.f; }
#pragma unroll
    for (int j = 0; j < 8; j++) {
#pragma unroll
        for (int t = 0; t < 16; t++) {
            int bi = (8 * t + lq) * (WROW / 2) + j * 8 + lr;
            mma(s[t], xa[0][j], Wh32[bi], Wh32[bi + 4]);
        }
#pragma unroll
        for (int t = 0; t < 16; t++) {
            int bi = (8 * t + lq) * (WROW / 2) + j * 8 + lr;
            mma(s[t], xa[1][j], Wh32[bi], Wh32[bi + 4]);
        }
#pragma unroll
        for (int t = 0; t < 16; t++) {
            int bi = (8 * t + lq) * (WROW / 2) + j * 8 + lr;
            mma(s[t], xa[0][j], Wl32[bi], Wl32[bi + 4]);
        }
    }

    if (which < 2) {
        // q and k: fp16 hi only (both lo-terms dropped in attention)
        __half* oh = (which == 0 ? g_qh : g_kh) + ((size_t)h * NT + n0 + w * 16) * D;
#pragma unroll
        for (int t = 0; t < 16; t++) {
            int col = 8 * t + lr * 2;
            *(uint32_t*)(oh + (size_t)lq * D + col)       = packhi(s[t][0], s[t][1]);
            *(uint32_t*)(oh + (size_t)(lq + 8) * D + col) = packhi(s[t][2], s[t][3]);
        }
    } else {
        // v: transpose 64 rows via smem, store [h][d][n] fp16 coalesced
        __syncthreads();
        float* buf = (float*)sm;   // [64][TP]
#pragma unroll
        for (int t = 0; t < 16; t++) {
            int c = 8 * t + lr * 2;
            int r0 = w * 16 + lq, r1 = r0 + 8;
            buf[r0 * TP + c] = s[t][0]; buf[r0 * TP + c + 1] = s[t][1];
            buf[r1 * TP + c] = s[t][2]; buf[r1 * TP + c + 1] = s[t][3];
        }
        __syncthreads();
#pragma unroll
        for (int dd = 0; dd < 32; dd++) {
            int d = w * 32 + dd;
            int n2 = l * 2;
            __half hb[2];
            hb[0] = __float2half_rn(buf[n2 * TP + d]);
            hb[1] = __float2half_rn(buf[(n2 + 1) * TP + d]);
            *(uint32_t*)(g_vh + ((size_t)h * D + d) * NT + n0 + n2) = *(uint32_t*)hb;
        }
    }
}

// ---------------- Wg transpose + final MLP --------------------------------------
__global__ void wgT_kernel(const float* __restrict__ Wg) {
    int it = blockIdx.x * 256 + threadIdx.x;
    if (it < D * D) {
        int d = it >> 7, f = it & 127;
        g_wgT[f * D + d] = Wg[d * D + f];
    }
}

// grid 256 (16 rows per CTA), 256 threads
__global__ void __launch_bounds__(256) final_kernel(const float* __restrict__ x,
                                                    const float* __restrict__ bg,
                                                    float* __restrict__ y) {
    __shared__ float hs[16][132];
    __shared__ float Ws[16][132];
    __shared__ float bsh[D];
    const int n0 = blockIdx.x * 16;
    const int tid = threadIdx.x;

    for (int it = tid; it < 16 * 32; it += 256) {
        int r = it >> 5, c4 = it & 31;
        size_t off = (size_t)(n0 + r) * D + c4 * 4;
        float4 a = *(const float4*)(x + off);
#pragma unroll
        for (int hh = 0; hh < H; hh++) {
            float4 b = *(const float4*)(g_o + (size_t)hh * NT * D + off);
            a.x += b.x; a.y += b.y; a.z += b.z; a.w += b.w;
        }
        *(float4*)&hs[r][c4 * 4] = a;
    }
    if (tid < D) bsh[tid] = bg[tid];

    const int ty = tid >> 4, tx = tid & 15;
    float acc[8];
#pragma unroll
    for (int j = 0; j < 8; j++) acc[j] = 0.f;

    for (int fc = 0; fc < 8; fc++) {
        __syncthreads();
        for (int it = tid; it < 16 * 32; it += 256) {
            int r = it >> 5, c4 = it & 31;
            *(float4*)&Ws[r][c4 * 4] = *(const float4*)(g_wgT + (size_t)(fc * 16 + r) * D + c4 * 4);
        }
        __syncthreads();
#pragma unroll
        for (int f = 0; f < 16; f++) {
            float a = hs[ty][fc * 16 + f];
            float4 b0 = *(float4*)&Ws[f][tx * 8];
            float4 b1 = *(float4*)&Ws[f][tx * 8 + 4];
            acc[0] = fmaf(a, b0.x, acc[0]); acc[1] = fmaf(a, b0.y, acc[1]);
            acc[2] = fmaf(a, b0.z, acc[2]); acc[3] = fmaf(a, b0.w, acc[3]);
            acc[4] = fmaf(a, b1.x, acc[4]); acc[5] = fmaf(a, b1.y, acc[5]);
            acc[6] = fmaf(a, b1.z, acc[6]); acc[7] = fmaf(a, b1.w, acc[7]);
        }
    }

    {
        int n = n0 + ty;
#pragma unroll
        for (int jj = 0; jj < 8; jj += 4) {
            int d = tx * 8 + jj;
            float4 xv = *(const float4*)(x + (size_t)n * D + d);
            float4 r;
            r.x = xv.x + fmaxf(acc[jj + 0] + bsh[d + 0], 0.f);
            r.y = xv.y + fmaxf(acc[jj + 1] + bsh[d + 1], 0.f);
            r.z = xv.z + fmaxf(acc[jj + 2] + bsh[d + 2], 0.f);
            r.w = xv.w + fmaxf(acc[jj + 3] + bsh[d + 3], 0.f);
            *(float4*)(y + (size_t)n * D + d) = r;
        }
    }
}

// ---------------- launch ---------------------------------------------------------
extern "C" void kernel_launch(void* const* d_in, const int* in_sizes, int n_in,
                              void* d_out, int out_size) {
    const float* x  = (const float*)d_in[0];
    const float* Wk = (const float*)d_in[1];
    const float* Wq = (const float*)d_in[2];
    const float* Wv = (const float*)d_in[3];
    const float* Wm = (const float*)d_in[4];
    const float* Wg = (const float*)d_in[5];
    const float* bg = (const float*)d_in[6];
    float* y = (float*)d_out;

    cudaFuncSetAttribute(attn_kernel, cudaFuncAttributeMaxDynamicSharedMemorySize, ASMEM);
    cudaFuncSetAttribute(qkv_mma_kernel, cudaFuncAttributeMaxDynamicSharedMemorySize, QSMEM);

    reset_ctr_kernel<<<1, 1>>>();
    splitx_kernel<<<NT * D / (256 * 8), 256>>>(x);
    splitW_kernel<<<dim3(H, 3), 256>>>(Wk, Wq, Wv);
    wgT_kernel<<<(D * D + 255) / 256, 256>>>(Wg);
    qkv_mma_kernel<<<dim3(NT / 64, H, 3), 128, QSMEM>>>();
    attn_kernel<<<PGRID, 128, ASMEM>>>(Wm);
    final_kernel<<<NT / 16, 256>>>(x, bg, y);
}

// round 16
// speedup vs baseline: 1.9326x; 1.0706x over previous
#include <cuda_runtime.h>
#include <cuda_fp16.h>
#include <cstdint>

#define NT 4096
#define D  128
#define H  8
#define BN 64
#define NB (NT / BN)
#define NBH (NB / 2)          // 32 key blocks per half
#define NTILES 1024           // 64 q-tiles x 8 heads x 2 key-halves
#define PGRID 456             // 3 CTAs/SM x 152 SMs

// ---------------- scratch globals ---------------------------------------------
__device__ __align__(16) __half g_qh[H * NT * D];
__device__ __align__(16) __half g_kh[H * NT * D];
__device__ __align__(16) __half g_vh[H * D * NT];   // transposed [h][d][n]
__device__ __align__(16) float  g_po[2][H * NT * D]; // unnormalized partial O
__device__ float g_pm[2][H * NT];                    // partial row max
__device__ float g_pl[2][H * NT];                    // partial row sum
__device__ __align__(16) float  g_o[H * NT * D];
__device__ float g_wgT[D * D];
__device__ unsigned int g_ctr;

__device__ __align__(16) __half g_xh[NT * D];
__device__ __align__(16) __half g_xl[NT * D];
__device__ __align__(16) __half g_wT[3][2][H * D * D];   // [which][hi/lo][h][dout][f]

// ---------------- helpers -------------------------------------------------------
__device__ __forceinline__ float ex2f(float x) {
    float y; asm("ex2.approx.ftz.f32 %0,%1;" : "=f"(y) : "f"(x)); return y;
}
#define CP16(d, s) asm volatile("cp.async.cg.shared.global [%0],[%1],16;" :: "r"(d), "l"(s) : "memory")
#define CPC()  asm volatile("cp.async.commit_group;" ::: "memory")
#define CPW0() asm volatile("cp.async.wait_group 0;" ::: "memory")
#define CPW1() asm volatile("cp.async.wait_group 1;" ::: "memory")

__device__ __forceinline__ uint32_t su32(const void* p) {
    return (uint32_t)__cvta_generic_to_shared(p);
}

__device__ __forceinline__ void mma(float* c, const uint32_t* a, uint32_t b0, uint32_t b1) {
    asm volatile(
        "mma.sync.aligned.m16n8k16.row.col.f32.f16.f16.f32 "
        "{%0,%1,%2,%3},{%4,%5,%6,%7},{%8,%9},{%0,%1,%2,%3};"
        : "+f"(c[0]), "+f"(c[1]), "+f"(c[2]), "+f"(c[3])
        : "r"(a[0]), "r"(a[1]), "r"(a[2]), "r"(a[3]), "r"(b0), "r"(b1));
}

__device__ __forceinline__ void pack2(float a, float b, uint32_t& hi, uint32_t& lo) {
    __half2 h = __floats2half2_rn(a, b);
    float2 f = __half22float2(h);
    __half2 r = __floats2half2_rn(a - f.x, b - f.y);
    hi = *(uint32_t*)&h; lo = *(uint32_t*)&r;
}

__device__ __forceinline__ uint32_t packhi(float a, float b) {
    __half2 h = __floats2half2_rn(a, b);
    return *(uint32_t*)&h;
}

// pack to fp16 pair AND accumulate the rounded-value sum (for consistent l)
__device__ __forceinline__ uint32_t packsum(float a, float b, float& acc) {
    __half2 h = __floats2half2_rn(a, b);
    float2 f = __half22float2(h);
    acc += f.x + f.y;
    return *(uint32_t*)&h;
}

// ================== attention smem: 2 stages of (Kh[64][136] | V[128][72]) ======
#define KST    17408
#define VST    18432
#define STG    (KST + VST)              // 35840
#define ASMEM  (2 * STG)                // 71680  -> 3 CTAs/SM

__device__ __forceinline__ void load_stage(uint32_t sb, int h, int kb, int tid, int slot) {
    size_t kof = (size_t)h * NT * D + (size_t)kb * BN * D;
    size_t vof = (size_t)h * D * NT + (size_t)kb * BN;
    uint32_t kbase = sb + (uint32_t)slot * STG;
    uint32_t vbase = kbase + KST;
    for (int c = tid; c < 1024; c += 128) {          // Kh: 64 rows x 16 chunks
        int r = c >> 4, k = c & 15;
        CP16(kbase + (uint32_t)(r * 272 + k * 16), g_kh + kof + (size_t)r * D + k * 8);
    }
    for (int c = tid; c < 1024; c += 128) {          // V: 128 dim-rows x 8 chunks
        int r = c >> 3, k = c & 7;
        CP16(vbase + (uint32_t)(r * 144 + k * 16), g_vh + vof + (size_t)r * NT + k * 8);
    }
}

__global__ void reset_ctr_kernel() { g_ctr = 0u; }

// ---------------- attention: persistent, split-K=2, 128 threads, 3 CTAs/SM ------
__global__ void __launch_bounds__(128, 3) attn_kernel() {
    extern __shared__ char sm[];
    __shared__ unsigned int sidx;
    const int tid = threadIdx.x, w = tid >> 5, l = tid & 31;
    const int lq = l >> 2, lr = l & 3;
    const uint32_t sb = su32(sm);
    const float L2E = 1.4426950408889634f;

    while (true) {
        if (tid == 0) sidx = atomicAdd(&g_ctr, 1u);
        __syncthreads();
        const unsigned int idx = sidx;
        if (idx >= NTILES) break;
        const int h  = (int)(idx >> 7);              // consecutive units share head
        const int q0 = (int)((idx >> 1) & 63) * 64;
        const int c  = (int)(idx & 1);               // key half
        const int kb0 = c * NBH;

        load_stage(sb, h, kb0, tid, 0); CPC();

        // Q fragments (fp16 hi only) — overlaps with async loads
        uint32_t qa[8][4];
        {
            const __half* qs = g_qh + ((size_t)h * NT + q0 + w * 16) * D;
#pragma unroll
            for (int j = 0; j < 8; j++) {
                const __half* base = qs + (size_t)lq * D + j * 16 + lr * 2;
                qa[j][0] = *(const uint32_t*)(base);
                qa[j][1] = *(const uint32_t*)(base + 8 * D);
                qa[j][2] = *(const uint32_t*)(base + 8);
                qa[j][3] = *(const uint32_t*)(base + 8 * D + 8);
            }
        }

        float o[16][4];
#pragma unroll
        for (int t = 0; t < 16; t++) { o[t][0] = o[t][1] = o[t][2] = o[t][3] = 0.f; }
        float m0 = -1e30f, m1 = -1e30f, l0 = 0.f, l1 = 0.f;

        for (int i = 0; i < NBH; i++) {
            __syncthreads();                 // all warps done reading slot (i+1)&1
            if (i + 1 < NBH) load_stage(sb, h, kb0 + i + 1, tid, (i + 1) & 1);
            CPC(); CPW1();                   // stage i complete
            __syncthreads();

            const char* stg = sm + (i & 1) * STG;
            const uint32_t* Kh32 = (const uint32_t*)(stg);
            const uint32_t* Vh32 = (const uint32_t*)(stg + KST);

            // ---- S = QhKh — single-term, accumulator-interleaved ----
            float s[8][4];
#pragma unroll
            for (int t = 0; t < 8; t++) { s[t][0] = s[t][1] = s[t][2] = s[t][3] = 0.f; }
#pragma unroll
            for (int j = 0; j < 8; j++) {
                uint32_t bh[8][2];
#pragma unroll
                for (int t = 0; t < 8; t++) {
                    int bi = (8 * t + lq) * 68 + j * 8 + lr;
                    bh[t][0] = Kh32[bi]; bh[t][1] = Kh32[bi + 4];
                }
#pragma unroll
                for (int t = 0; t < 8; t++) mma(s[t], qa[j], bh[t][0], bh[t][1]);
            }

            // ---- online softmax ----
            float rx0 = -1e30f, rx1 = -1e30f;
#pragma unroll
            for (int t = 0; t < 8; t++) {
                rx0 = fmaxf(rx0, fmaxf(s[t][0], s[t][1]));
                rx1 = fmaxf(rx1, fmaxf(s[t][2], s[t][3]));
            }
            rx0 = fmaxf(rx0, __shfl_xor_sync(~0u, rx0, 1));
            rx0 = fmaxf(rx0, __shfl_xor_sync(~0u, rx0, 2));
            rx1 = fmaxf(rx1, __shfl_xor_sync(~0u, rx1, 1));
            rx1 = fmaxf(rx1, __shfl_xor_sync(~0u, rx1, 2));
            float mn0 = fmaxf(m0, rx0), mn1 = fmaxf(m1, rx1);
            float sc0 = ex2f((m0 - mn0) * L2E), sc1 = ex2f((m1 - mn1) * L2E);
            m0 = mn0; m1 = mn1;
#pragma unroll
            for (int t = 0; t < 8; t++) {
                s[t][0] = ex2f((s[t][0] - mn0) * L2E);
                s[t][1] = ex2f((s[t][1] - mn0) * L2E);
                s[t][2] = ex2f((s[t][2] - mn1) * L2E);
                s[t][3] = ex2f((s[t][3] - mn1) * L2E);
            }

            // ---- pack P (fp16) and sum the ROUNDED values for l ----
            float rs0 = 0.f, rs1 = 0.f;
            uint32_t ph[4][4];
#pragma unroll
            for (int j = 0; j < 4; j++) {
                ph[j][0] = packsum(s[2 * j][0],     s[2 * j][1],     rs0);
                ph[j][1] = packsum(s[2 * j][2],     s[2 * j][3],     rs1);
                ph[j][2] = packsum(s[2 * j + 1][0], s[2 * j + 1][1], rs0);
                ph[j][3] = packsum(s[2 * j + 1][2], s[2 * j + 1][3], rs1);
            }
            rs0 += __shfl_xor_sync(~0u, rs0, 1); rs0 += __shfl_xor_sync(~0u, rs0, 2);
            rs1 += __shfl_xor_sync(~0u, rs1, 1); rs1 += __shfl_xor_sync(~0u, rs1, 2);
            l0 = l0 * sc0 + rs0; l1 = l1 * sc1 + rs1;
#pragma unroll
            for (int t = 0; t < 16; t++) {
                o[t][0] *= sc0; o[t][1] *= sc0; o[t][2] *= sc1; o[t][3] *= sc1;
            }

            // ---- O += PhVh — accumulator-interleaved sweep ----
#pragma unroll
            for (int j = 0; j < 4; j++) {
                uint32_t vb[16][2];
#pragma unroll
                for (int t = 0; t < 16; t++) {
                    int bi = (8 * t + lq) * 36 + j * 8 + lr;
                    vb[t][0] = Vh32[bi]; vb[t][1] = Vh32[bi + 4];
                }
#pragma unroll
                for (int t = 0; t < 16; t++) mma(o[t], ph[j], vb[t][0], vb[t][1]);
            }
        }

        // ---- epilogue: write UNNORMALIZED partials ----
        const int r0 = h * NT + q0 + w * 16 + lq;    // global row indices
        const int r1 = r0 + 8;
        float* po = g_po[c];
#pragma unroll
        for (int t = 0; t < 16; t++) {
            int col = 8 * t + lr * 2;
            *(float2*)(po + (size_t)r0 * D + col) = make_float2(o[t][0], o[t][1]);
            *(float2*)(po + (size_t)r1 * D + col) = make_float2(o[t][2], o[t][3]);
        }
        if (lr == 0) {
            g_pm[c][r0] = m0; g_pl[c][r0] = l0;
            g_pm[c][r1] = m1; g_pl[c][r1] = l1;
        }
        __syncthreads();   // smem reads done before next tile's prologue loads
    }
}

// ---------------- merge: combine key halves exactly (fp32 LSE merge) ------------
// grid H*NT/8 = 4096, 256 threads: each warp merges one row, lane = 4 dims
__global__ void __launch_bounds__(256) merge_kernel(const float* __restrict__ W_m) {
    const int row = blockIdx.x * 8 + (threadIdx.x >> 5);
    const int lane = threadIdx.x & 31;
    const float L2E = 1.4426950408889634f;
    const int h = row >> 12;
    float m0 = g_pm[0][row], m1 = g_pm[1][row];
    float l0 = g_pl[0][row], l1 = g_pl[1][row];
    float m = fmaxf(m0, m1);
    float e0 = ex2f((m0 - m) * L2E), e1 = ex2f((m1 - m) * L2E);
    float inv = W_m[h] / (l0 * e0 + l1 * e1);
    float s0 = e0 * inv, s1 = e1 * inv;
    size_t base = (size_t)row * D + lane * 4;
    float4 a = *(const float4*)(g_po[0] + base);
    float4 b = *(const float4*)(g_po[1] + base);
    float4 r;
    r.x = a.x * s0 + b.x * s1; r.y = a.y * s0 + b.y * s1;
    r.z = a.z * s0 + b.z * s1; r.w = a.w * s0 + b.w * s1;
    *(float4*)(g_o + base) = r;
}

// ================== prep: split x, split+transpose W ============================
__global__ void __launch_bounds__(256) splitx_kernel(const float* __restrict__ x) {
    int base = (blockIdx.x * 256 + threadIdx.x) * 8;
    float4 a = *(const float4*)(x + base);
    float4 b = *(const float4*)(x + base + 4);
    float v[8] = {a.x, a.y, a.z, a.w, b.x, b.y, b.z, b.w};
    __align__(16) __half hb[8], lb[8];
#pragma unroll
    for (int i = 0; i < 8; i++) {
        __half hh = __float2half_rn(v[i]);
        hb[i] = hh;
        lb[i] = __float2half_rn(v[i] - __half2float(hh));
    }
    *(uint4*)(g_xh + base) = *(uint4*)hb;
    *(uint4*)(g_xl + base) = *(uint4*)lb;
}

__global__ void __launch_bounds__(256) splitW_kernel(const float* __restrict__ Wk,
                                                     const float* __restrict__ Wq,
                                                     const float* __restrict__ Wv) {
    const int h = blockIdx.x, which = blockIdx.y;
    const float* W = (which == 0 ? Wq : which == 1 ? Wk : Wv) + (size_t)h * D * D;
    __half* oh = g_wT[which][0] + (size_t)h * D * D;
    __half* ol = g_wT[which][1] + (size_t)h * D * D;
    for (int idx = threadIdx.x; idx < D * D; idx += 256) {
        int dout = idx >> 7, f = idx & 127;
        float v = W[(size_t)f * D + dout];
        __half hh = __float2half_rn(v);
        oh[idx] = hh;
        ol[idx] = __float2half_rn(v - __half2float(hh));
    }
}

// ================== qkv via HMMA: grid (64, 8, 3), 128 threads, 3 CTAs/SM ======
#define WROW 136
#define QST  (128 * WROW * 2)
#define QSMEM (2 * QST)
#define TP 133

__global__ void __launch_bounds__(128, 3) qkv_mma_kernel() {
    extern __shared__ char sm[];
    const int tid = threadIdx.x, w = tid >> 5, l = tid & 31;
    const int tile = blockIdx.x, h = blockIdx.y, which = blockIdx.z;
    const int lq = l >> 2, lr = l & 3;
    const int n0 = tile * 64;

    {
        const uint32_t sb = su32(sm);
        const __half* wh = g_wT[which][0] + (size_t)h * D * D;
        const __half* wl = g_wT[which][1] + (size_t)h * D * D;
        for (int c = tid; c < 2048; c += 128) {
            int r = c >> 4, k = c & 15;
            uint32_t so = (uint32_t)(r * (WROW * 2) + k * 16);
            CP16(sb + so,       wh + (size_t)r * D + k * 8);
            CP16(sb + QST + so, wl + (size_t)r * D + k * 8);
        }
        CPC();
    }

    uint32_t xa[2][8][4];
#pragma unroll
    for (int s = 0; s < 2; s++) {
        const __half* xs = (s ? g_xl : g_xh) + (size_t)(n0 + w * 16) * D;
#pragma unroll
        for (int j = 0; j < 8; j++) {
            const __half* base = xs + (size_t)lq * D + j * 16 + lr * 2;
            xa[s][j][0] = *(const uint32_t*)(base);
            xa[s][j][1] = *(const uint32_t*)(base + 8 * D);
            xa[s][j][2] = *(const uint32_t*)(base + 8);
            xa[s][j][3] = *(const uint32_t*)(base + 8 * D + 8);
        }
    }

    CPW0();
    __syncthreads();

    const uint32_t* Wh32 = (const uint32_t*)(sm);
    const uint32_t* Wl32 = (const uint32_t*)(sm + QST);

    float s[16][4];
#pragma unroll
    for (int t = 0; t < 16; t++) { s[t][0] = s[t][1] = s[t][2] = s[t][3] = 0.f; }
#pragma unroll
    for (int j = 0; j < 8; j++) {
#pragma unroll
        for (int t = 0; t < 16; t++) {
            int bi = (8 * t + lq) * (WROW / 2) + j * 8 + lr;
            mma(s[t], xa[0][j], Wh32[bi], Wh32[bi + 4]);
        }
#pragma unroll
        for (int t = 0; t < 16; t++) {
            int bi = (8 * t + lq) * (WROW / 2) + j * 8 + lr;
            mma(s[t], xa[1][j], Wh32[bi], Wh32[bi + 4]);
        }
#pragma unroll
        for (int t = 0; t < 16; t++) {
            int bi = (8 * t + lq) * (WROW / 2) + j * 8 + lr;
            mma(s[t], xa[0][j], Wl32[bi], Wl32[bi + 4]);
        }
    }

    if (which < 2) {
        // q and k: fp16 hi only (both lo-terms dropped in attention)
        __half* oh = (which == 0 ? g_qh : g_kh) + ((size_t)h * NT + n0 + w * 16) * D;
#pragma unroll
        for (int t = 0; t < 16; t++) {
            int col = 8 * t + lr * 2;
            *(uint32_t*)(oh + (size_t)lq * D + col)       = packhi(s[t][0], s[t][1]);
            *(uint32_t*)(oh + (size_t)(lq + 8) * D + col) = packhi(s[t][2], s[t][3]);
        }
    } else {
        // v: transpose 64 rows via smem, store [h][d][n] fp16 coalesced
        __syncthreads();
        float* buf = (float*)sm;   // [64][TP]
#pragma unroll
        for (int t = 0; t < 16; t++) {
            int c = 8 * t + lr * 2;
            int r0 = w * 16 + lq, r1 = r0 + 8;
            buf[r0 * TP + c] = s[t][0]; buf[r0 * TP + c + 1] = s[t][1];
            buf[r1 * TP + c] = s[t][2]; buf[r1 * TP + c + 1] = s[t][3];
        }
        __syncthreads();
#pragma unroll
        for (int dd = 0; dd < 32; dd++) {
            int d = w * 32 + dd;
            int n2 = l * 2;
            __half hb[2];
            hb[0] = __float2half_rn(buf[n2 * TP + d]);
            hb[1] = __float2half_rn(buf[(n2 + 1) * TP + d]);
            *(uint32_t*)(g_vh + ((size_t)h * D + d) * NT + n0 + n2) = *(uint32_t*)hb;
        }
    }
}

// ---------------- Wg transpose + final MLP --------------------------------------
__global__ void wgT_kernel(const float* __restrict__ Wg) {
    int it = blockIdx.x * 256 + threadIdx.x;
    if (it < D * D) {
        int d = it >> 7, f = it & 127;
        g_wgT[f * D + d] = Wg[d * D + f];
    }
}

// grid 256 (16 rows per CTA), 256 threads
__global__ void __launch_bounds__(256) final_kernel(const float* __restrict__ x,
                                                    const float* __restrict__ bg,
                                                    float* __restrict__ y) {
    __shared__ float hs[16][132];
    __shared__ float Ws[16][132];
    __shared__ float bsh[D];
    const int n0 = blockIdx.x * 16;
    const int tid = threadIdx.x;

    for (int it = tid; it < 16 * 32; it += 256) {
        int r = it >> 5, c4 = it & 31;
        size_t off = (size_t)(n0 + r) * D + c4 * 4;
        float4 a = *(const float4*)(x + off);
#pragma unroll
        for (int hh = 0; hh < H; hh++) {
            float4 b = *(const float4*)(g_o + (size_t)hh * NT * D + off);
            a.x += b.x; a.y += b.y; a.z += b.z; a.w += b.w;
        }
        *(float4*)&hs[r][c4 * 4] = a;
    }
    if (tid < D) bsh[tid] = bg[tid];

    const int ty = tid >> 4, tx = tid & 15;
    float acc[8];
#pragma unroll
    for (int j = 0; j < 8; j++) acc[j] = 0.f;

    for (int fc = 0; fc < 8; fc++) {
        __syncthreads();
        for (int it = tid; it < 16 * 32; it += 256) {
            int r = it >> 5, c4 = it & 31;
            *(float4*)&Ws[r][c4 * 4] = *(const float4*)(g_wgT + (size_t)(fc * 16 + r) * D + c4 * 4);
        }
        __syncthreads();
#pragma unroll
        for (int f = 0; f < 16; f++) {
            float a = hs[ty][fc * 16 + f];
            float4 b0 = *(float4*)&Ws[f][tx * 8];
            float4 b1 = *(float4*)&Ws[f][tx * 8 + 4];
            acc[0] = fmaf(a, b0.x, acc[0]); acc[1] = fmaf(a, b0.y, acc[1]);
            acc[2] = fmaf(a, b0.z, acc[2]); acc[3] = fmaf(a, b0.w, acc[3]);
            acc[4] = fmaf(a, b1.x, acc[4]); acc[5] = fmaf(a, b1.y, acc[5]);
            acc[6] = fmaf(a, b1.z, acc[6]); acc[7] = fmaf(a, b1.w, acc[7]);
        }
    }

    {
        int n = n0 + ty;
#pragma unroll
        for (int jj = 0; jj < 8; jj += 4) {
            int d = tx * 8 + jj;
            float4 xv = *(const float4*)(x + (size_t)n * D + d);
            float4 r;
            r.x = xv.x + fmaxf(acc[jj + 0] + bsh[d + 0], 0.f);
            r.y = xv.y + fmaxf(acc[jj + 1] + bsh[d + 1], 0.f);
            r.z = xv.z + fmaxf(acc[jj + 2] + bsh[d + 2], 0.f);
            r.w = xv.w + fmaxf(acc[jj + 3] + bsh[d + 3], 0.f);
            *(float4*)(y + (size_t)n * D + d) = r;
        }
    }
}

// ---------------- launch ---------------------------------------------------------
extern "C" void kernel_launch(void* const* d_in, const int* in_sizes, int n_in,
                              void* d_out, int out_size) {
    const float* x  = (const float*)d_in[0];
    const float* Wk = (const float*)d_in[1];
    const float* Wq = (const float*)d_in[2];
    const float* Wv = (const float*)d_in[3];
    const float* Wm = (const float*)d_in[4];
    const float* Wg = (const float*)d_in[5];
    const float* bg = (const float*)d_in[6];
    float* y = (float*)d_out;

    cudaFuncSetAttribute(attn_kernel, cudaFuncAttributeMaxDynamicSharedMemorySize, ASMEM);
    cudaFuncSetAttribute(qkv_mma_kernel, cudaFuncAttributeMaxDynamicSharedMemorySize, QSMEM);

    reset_ctr_kernel<<<1, 1>>>();
    splitx_kernel<<<NT * D / (256 * 8), 256>>>(x);
    splitW_kernel<<<dim3(H, 3), 256>>>(Wk, Wq, Wv);
    wgT_kernel<<<(D * D + 255) / 256, 256>>>(Wg);
    qkv_mma_kernel<<<dim3(NT / 64, H, 3), 128, QSMEM>>>();
    attn_kernel<<<PGRID, 128, ASMEM>>>();
    merge_kernel<<<H * NT / 8, 256>>>(Wm);
    final_kernel<<<NT / 16, 256>>>(x, bg, y);
}